// round 1
// baseline (speedup 1.0000x reference)
#include <cuda_runtime.h>
#include <cstdint>
#include <math.h>

#define T_SEQ   4096
#define DM      1024
#define DFF     4096
#define NHEADS  16
#define HDIM    64
#define LN_EPS  1e-5f

// ---------------- scratch (static device globals; no allocation) ----------------
static __device__ float g_ln [T_SEQ * DM];        // 16 MB
static __device__ float g_qkv[T_SEQ * 3 * DM];    // 48 MB
static __device__ float g_y  [T_SEQ * DM];        // 16 MB
static __device__ float g_x2 [T_SEQ * DM];        // 16 MB
static __device__ float g_ff [T_SEQ * DFF];       // 64 MB

// ---------------- helpers ----------------
__device__ __forceinline__ float to_tf32(float x) {
    uint32_t u;
    asm("cvt.rna.tf32.f32 %0, %1;" : "=r"(u) : "f"(x));
    return __uint_as_float(u);
}

__device__ __forceinline__ void mma_tf32(float* c,
    uint32_t a0, uint32_t a1, uint32_t a2, uint32_t a3,
    uint32_t b0, uint32_t b1)
{
    asm volatile(
        "mma.sync.aligned.m16n8k8.row.col.f32.tf32.tf32.f32 "
        "{%0,%1,%2,%3}, {%4,%5,%6,%7}, {%8,%9}, {%0,%1,%2,%3};\n"
        : "+f"(c[0]), "+f"(c[1]), "+f"(c[2]), "+f"(c[3])
        : "r"(a0), "r"(a1), "r"(a2), "r"(a3), "r"(b0), "r"(b1));
}

__device__ __forceinline__ float gelu_exact(float v) {
    return 0.5f * v * (1.0f + erff(v * 0.70710678118654752440f));
}

// ---------------- LayerNorm: one block per row of 1024 ----------------
__global__ __launch_bounds__(256) void ln_kernel(
    const float* __restrict__ x, const float* __restrict__ g,
    const float* __restrict__ b, float* __restrict__ out)
{
    int row = blockIdx.x;
    int tid = threadIdx.x;
    const float4 v = ((const float4*)(x + (size_t)row * DM))[tid];
    float s  = v.x + v.y + v.z + v.w;
    float sq = v.x * v.x + v.y * v.y + v.z * v.z + v.w * v.w;
    #pragma unroll
    for (int o = 16; o; o >>= 1) {
        s  += __shfl_xor_sync(0xffffffffu, s,  o);
        sq += __shfl_xor_sync(0xffffffffu, sq, o);
    }
    __shared__ float ss[8], ssq[8];
    __shared__ float mean_s, inv_s;
    int w = tid >> 5, l = tid & 31;
    if (l == 0) { ss[w] = s; ssq[w] = sq; }
    __syncthreads();
    if (tid == 0) {
        float st = 0.f, sqt = 0.f;
        #pragma unroll
        for (int i = 0; i < 8; i++) { st += ss[i]; sqt += ssq[i]; }
        float mean = st * (1.0f / DM);
        float var  = sqt * (1.0f / DM) - mean * mean;
        mean_s = mean;
        inv_s  = rsqrtf(var + LN_EPS);
    }
    __syncthreads();
    float mean = mean_s, inv = inv_s;
    const float4 gv = ((const float4*)g)[tid];
    const float4 bv = ((const float4*)b)[tid];
    float4 o;
    o.x = (v.x - mean) * inv * gv.x + bv.x;
    o.y = (v.y - mean) * inv * gv.y + bv.y;
    o.z = (v.z - mean) * inv * gv.z + bv.z;
    o.w = (v.w - mean) * inv * gv.w + bv.w;
    ((float4*)(out + (size_t)row * DM))[tid] = o;
}

// ---------------- TF32 GEMM: C[M,N] = A[M,K] @ B[K,N] + epilogue ----------------
// MODE 0: +bias   MODE 1: +bias+res   MODE 2: gelu(+bias)
// BM=128, BN=128, BK=16, 256 threads (8 warps, 2x4), warp tile 64x32.
template<int MODE>
__global__ __launch_bounds__(256) void gemm_tf32(
    const float* __restrict__ A, const float* __restrict__ B,
    const float* __restrict__ bias, const float* __restrict__ res,
    float* __restrict__ C, int M, int N, int K)
{
    __shared__ float As[2][16][132];   // transposed: As[k][m]
    __shared__ float Bs[2][16][132];   // Bs[k][n]

    const int tid  = threadIdx.x;
    const int lane = tid & 31, w = tid >> 5;
    const int wm = w >> 2, wn = w & 3;          // 2 x 4 warp grid
    const int gp = lane >> 2, tg = lane & 3;    // groupID, thread-in-group
    const int m0 = blockIdx.y * 128, n0 = blockIdx.x * 128;

    float c[4][4][4];
    #pragma unroll
    for (int i = 0; i < 4; i++)
        #pragma unroll
        for (int j = 0; j < 4; j++)
            #pragma unroll
            for (int r = 0; r < 4; r++) c[i][j][r] = 0.f;

    const int KT = K >> 4;
    float4 va[2], vb[2];

    // --- load tile 0 ---
    #pragma unroll
    for (int i = 0; i < 2; i++) {
        int idx = tid + i * 256;
        int r = idx >> 2, c4 = (idx & 3) << 2;
        va[i] = *(const float4*)(A + (size_t)(m0 + r) * K + c4);
        int rb = idx >> 5, cb = (idx & 31) << 2;
        vb[i] = *(const float4*)(B + (size_t)rb * N + n0 + cb);
    }
    #pragma unroll
    for (int i = 0; i < 2; i++) {
        int idx = tid + i * 256;
        int r = idx >> 2, c4 = (idx & 3) << 2;
        As[0][c4 + 0][r] = to_tf32(va[i].x);
        As[0][c4 + 1][r] = to_tf32(va[i].y);
        As[0][c4 + 2][r] = to_tf32(va[i].z);
        As[0][c4 + 3][r] = to_tf32(va[i].w);
        int rb = idx >> 5, cb = (idx & 31) << 2;
        float4 t; t.x = to_tf32(vb[i].x); t.y = to_tf32(vb[i].y);
        t.z = to_tf32(vb[i].z); t.w = to_tf32(vb[i].w);
        *(float4*)&Bs[0][rb][cb] = t;
    }
    __syncthreads();

    int cur = 0;
    for (int kt = 0; kt < KT; kt++) {
        if (kt + 1 < KT) {
            #pragma unroll
            for (int i = 0; i < 2; i++) {
                int idx = tid + i * 256;
                int r = idx >> 2, c4 = (idx & 3) << 2;
                va[i] = *(const float4*)(A + (size_t)(m0 + r) * K + (kt + 1) * 16 + c4);
                int rb = idx >> 5, cb = (idx & 31) << 2;
                vb[i] = *(const float4*)(B + (size_t)((kt + 1) * 16 + rb) * N + n0 + cb);
            }
        }
        // --- compute on buffer cur ---
        #pragma unroll
        for (int ks = 0; ks < 2; ks++) {
            const int k = ks * 8;
            uint32_t a[4][4], b[4][2];
            #pragma unroll
            for (int mf = 0; mf < 4; mf++) {
                int r0 = wm * 64 + mf * 16;
                a[mf][0] = __float_as_uint(As[cur][k + tg    ][r0 + gp    ]);
                a[mf][1] = __float_as_uint(As[cur][k + tg    ][r0 + gp + 8]);
                a[mf][2] = __float_as_uint(As[cur][k + tg + 4][r0 + gp    ]);
                a[mf][3] = __float_as_uint(As[cur][k + tg + 4][r0 + gp + 8]);
            }
            #pragma unroll
            for (int nf = 0; nf < 4; nf++) {
                int c0 = wn * 32 + nf * 8;
                b[nf][0] = __float_as_uint(Bs[cur][k + tg    ][c0 + gp]);
                b[nf][1] = __float_as_uint(Bs[cur][k + tg + 4][c0 + gp]);
            }
            #pragma unroll
            for (int mf = 0; mf < 4; mf++)
                #pragma unroll
                for (int nf = 0; nf < 4; nf++)
                    mma_tf32(c[mf][nf], a[mf][0], a[mf][1], a[mf][2], a[mf][3],
                             b[nf][0], b[nf][1]);
        }
        if (kt + 1 < KT) {
            int nxt = cur ^ 1;
            #pragma unroll
            for (int i = 0; i < 2; i++) {
                int idx = tid + i * 256;
                int r = idx >> 2, c4 = (idx & 3) << 2;
                As[nxt][c4 + 0][r] = to_tf32(va[i].x);
                As[nxt][c4 + 1][r] = to_tf32(va[i].y);
                As[nxt][c4 + 2][r] = to_tf32(va[i].z);
                As[nxt][c4 + 3][r] = to_tf32(va[i].w);
                int rb = idx >> 5, cb = (idx & 31) << 2;
                float4 t; t.x = to_tf32(vb[i].x); t.y = to_tf32(vb[i].y);
                t.z = to_tf32(vb[i].z); t.w = to_tf32(vb[i].w);
                *(float4*)&Bs[nxt][rb][cb] = t;
            }
            __syncthreads();
            cur = nxt;
        }
    }

    // --- epilogue ---
    #pragma unroll
    for (int mf = 0; mf < 4; mf++) {
        #pragma unroll
        for (int nf = 0; nf < 4; nf++) {
            int col = n0 + wn * 32 + nf * 8 + 2 * tg;
            float bi0 = bias[col], bi1 = bias[col + 1];
            #pragma unroll
            for (int h = 0; h < 2; h++) {
                int row = m0 + wm * 64 + mf * 16 + gp + h * 8;
                float v0 = c[mf][nf][h * 2 + 0] + bi0;
                float v1 = c[mf][nf][h * 2 + 1] + bi1;
                if (MODE == 1) {
                    const float2 rv = *(const float2*)(res + (size_t)row * N + col);
                    v0 += rv.x; v1 += rv.y;
                }
                if (MODE == 2) { v0 = gelu_exact(v0); v1 = gelu_exact(v1); }
                float2 o; o.x = v0; o.y = v1;
                *(float2*)(C + (size_t)row * N + col) = o;
            }
        }
    }
}

// ---------------- causal flash attention ----------------
// grid (qt=64, h=16), 256 threads (8 warps 2x4), 64-query x 64-key tiles, head=64
#define AST 68
#define ATTN_SMEM ((4 * 64 * AST + 3 * 64) * 4 + 64 * 4)

__global__ __launch_bounds__(256) void attn_kernel(
    const float* __restrict__ qkv, const int* __restrict__ amask,
    float* __restrict__ y)
{
    extern __shared__ float sm[];
    float* Qs   = sm;
    float* Ks   = Qs + 64 * AST;
    float* Vs   = Ks + 64 * AST;
    float* Ss   = Vs + 64 * AST;
    float* m_s  = Ss + 64 * AST;
    float* l_s  = m_s + 64;
    float* al_s = l_s + 64;
    int*   msk  = (int*)(al_s + 64);

    const int tid = threadIdx.x, lane = tid & 31, w = tid >> 5;
    const int wm = w >> 2, wn = w & 3;
    const int gp = lane >> 2, tg = lane & 3;
    const int h = blockIdx.y, qt = blockIdx.x;

    // load Q tile (rounded to tf32)
    #pragma unroll
    for (int i = 0; i < 4; i++) {
        int idx = tid + i * 256;
        int r = idx >> 4, c4 = (idx & 15) << 2;
        const float4 v = *(const float4*)(qkv + (size_t)(qt * 64 + r) * (3 * DM) + h * HDIM + c4);
        Qs[r * AST + c4 + 0] = to_tf32(v.x);
        Qs[r * AST + c4 + 1] = to_tf32(v.y);
        Qs[r * AST + c4 + 2] = to_tf32(v.z);
        Qs[r * AST + c4 + 3] = to_tf32(v.w);
    }
    if (tid < 64) { m_s[tid] = -INFINITY; l_s[tid] = 0.f; }

    float o[2][2][4];
    #pragma unroll
    for (int i = 0; i < 2; i++)
        #pragma unroll
        for (int j = 0; j < 2; j++)
            #pragma unroll
            for (int r = 0; r < 4; r++) o[i][j][r] = 0.f;

    __syncthreads();

    for (int kt = 0; kt <= qt; kt++) {
        // load K, V tiles + mask
        #pragma unroll
        for (int i = 0; i < 4; i++) {
            int idx = tid + i * 256;
            int r = idx >> 4, c4 = (idx & 15) << 2;
            size_t base = (size_t)(kt * 64 + r) * (3 * DM) + h * HDIM + c4;
            const float4 kv = *(const float4*)(qkv + base + DM);
            const float4 vv = *(const float4*)(qkv + base + 2 * DM);
            Ks[r * AST + c4 + 0] = to_tf32(kv.x);
            Ks[r * AST + c4 + 1] = to_tf32(kv.y);
            Ks[r * AST + c4 + 2] = to_tf32(kv.z);
            Ks[r * AST + c4 + 3] = to_tf32(kv.w);
            Vs[r * AST + c4 + 0] = to_tf32(vv.x);
            Vs[r * AST + c4 + 1] = to_tf32(vv.y);
            Vs[r * AST + c4 + 2] = to_tf32(vv.z);
            Vs[r * AST + c4 + 3] = to_tf32(vv.w);
        }
        if (tid < 64) msk[tid] = amask[kt * 64 + tid];
        __syncthreads();

        // S = Q @ K^T  (warp tile 32x16 of the 64x64 S)
        float sc[2][2][4];
        #pragma unroll
        for (int i = 0; i < 2; i++)
            #pragma unroll
            for (int j = 0; j < 2; j++)
                #pragma unroll
                for (int r = 0; r < 4; r++) sc[i][j][r] = 0.f;

        #pragma unroll
        for (int ks = 0; ks < 8; ks++) {
            const int k = ks * 8;
            uint32_t a[2][4], b[2][2];
            #pragma unroll
            for (int mf = 0; mf < 2; mf++) {
                int r0 = wm * 32 + mf * 16;
                a[mf][0] = __float_as_uint(Qs[(r0 + gp    ) * AST + k + tg    ]);
                a[mf][1] = __float_as_uint(Qs[(r0 + gp + 8) * AST + k + tg    ]);
                a[mf][2] = __float_as_uint(Qs[(r0 + gp    ) * AST + k + tg + 4]);
                a[mf][3] = __float_as_uint(Qs[(r0 + gp + 8) * AST + k + tg + 4]);
            }
            #pragma unroll
            for (int nf = 0; nf < 2; nf++) {
                int c0 = wn * 16 + nf * 8;
                b[nf][0] = __float_as_uint(Ks[(c0 + gp) * AST + k + tg    ]);
                b[nf][1] = __float_as_uint(Ks[(c0 + gp) * AST + k + tg + 4]);
            }
            #pragma unroll
            for (int mf = 0; mf < 2; mf++)
                #pragma unroll
                for (int nf = 0; nf < 2; nf++)
                    mma_tf32(sc[mf][nf], a[mf][0], a[mf][1], a[mf][2], a[mf][3],
                             b[nf][0], b[nf][1]);
        }

        // scale + causal/attn mask, write S to smem
        #pragma unroll
        for (int mf = 0; mf < 2; mf++) {
            #pragma unroll
            for (int nf = 0; nf < 2; nf++) {
                int cc = wn * 16 + nf * 8 + 2 * tg;
                #pragma unroll
                for (int hh = 0; hh < 2; hh++) {
                    int r = wm * 32 + mf * 16 + gp + hh * 8;
                    int qg = qt * 64 + r;
                    #pragma unroll
                    for (int j = 0; j < 2; j++) {
                        int kg = kt * 64 + cc + j;
                        float sv = sc[mf][nf][hh * 2 + j] * 0.125f;
                        bool ok = (kg <= qg) && (msk[cc + j] != 0);
                        Ss[r * AST + cc + j] = ok ? sv : -INFINITY;
                    }
                }
            }
        }
        __syncthreads();

        // online softmax: 4 threads per row
        {
            int r = tid >> 2, sub = tid & 3;
            float mprev = m_s[r];
            float* srow = Ss + r * AST + sub * 16;
            float tmax = -INFINITY;
            #pragma unroll
            for (int j = 0; j < 16; j++) tmax = fmaxf(tmax, srow[j]);
            tmax = fmaxf(tmax, __shfl_xor_sync(0xffffffffu, tmax, 1));
            tmax = fmaxf(tmax, __shfl_xor_sync(0xffffffffu, tmax, 2));
            float nm  = fmaxf(mprev, tmax);
            float nme = fmaxf(nm, -1e30f);
            float ps = 0.f;
            #pragma unroll
            for (int j = 0; j < 16; j++) {
                float p = __expf(srow[j] - nme);
                ps += p;
                srow[j] = to_tf32(p);
            }
            ps += __shfl_xor_sync(0xffffffffu, ps, 1);
            ps += __shfl_xor_sync(0xffffffffu, ps, 2);
            if (sub == 0) {
                float alpha = __expf(mprev - nme);
                m_s[r]  = nm;
                l_s[r]  = l_s[r] * alpha + ps;
                al_s[r] = alpha;
            }
        }
        __syncthreads();

        // O = O*alpha + P @ V
        #pragma unroll
        for (int mf = 0; mf < 2; mf++) {
            int r0 = wm * 32 + mf * 16;
            float alo = al_s[r0 + gp], ahi = al_s[r0 + gp + 8];
            #pragma unroll
            for (int nf = 0; nf < 2; nf++) {
                o[mf][nf][0] *= alo; o[mf][nf][1] *= alo;
                o[mf][nf][2] *= ahi; o[mf][nf][3] *= ahi;
            }
        }
        #pragma unroll
        for (int ks = 0; ks < 8; ks++) {
            const int k = ks * 8;
            uint32_t a[2][4], b[2][2];
            #pragma unroll
            for (int mf = 0; mf < 2; mf++) {
                int r0 = wm * 32 + mf * 16;
                a[mf][0] = __float_as_uint(Ss[(r0 + gp    ) * AST + k + tg    ]);
                a[mf][1] = __float_as_uint(Ss[(r0 + gp + 8) * AST + k + tg    ]);
                a[mf][2] = __float_as_uint(Ss[(r0 + gp    ) * AST + k + tg + 4]);
                a[mf][3] = __float_as_uint(Ss[(r0 + gp + 8) * AST + k + tg + 4]);
            }
            #pragma unroll
            for (int nf = 0; nf < 2; nf++) {
                int c0 = wn * 16 + nf * 8;
                b[nf][0] = __float_as_uint(Vs[(k + tg    ) * AST + c0 + gp]);
                b[nf][1] = __float_as_uint(Vs[(k + tg + 4) * AST + c0 + gp]);
            }
            #pragma unroll
            for (int mf = 0; mf < 2; mf++)
                #pragma unroll
                for (int nf = 0; nf < 2; nf++)
                    mma_tf32(o[mf][nf], a[mf][0], a[mf][1], a[mf][2], a[mf][3],
                             b[nf][0], b[nf][1]);
        }
        __syncthreads();
    }

    // final: O / l -> y[t, h*64 + d]
    #pragma unroll
    for (int mf = 0; mf < 2; mf++) {
        int r0 = wm * 32 + mf * 16;
        float ilo = 1.0f / fmaxf(l_s[r0 + gp    ], 1e-30f);
        float ihi = 1.0f / fmaxf(l_s[r0 + gp + 8], 1e-30f);
        #pragma unroll
        for (int nf = 0; nf < 2; nf++) {
            int cc = wn * 16 + nf * 8 + 2 * tg;
            int t0 = qt * 64 + r0 + gp;
            float2 v0; v0.x = o[mf][nf][0] * ilo; v0.y = o[mf][nf][1] * ilo;
            *(float2*)(y + (size_t)t0 * DM + h * HDIM + cc) = v0;
            float2 v1; v1.x = o[mf][nf][2] * ihi; v1.y = o[mf][nf][3] * ihi;
            *(float2*)(y + (size_t)(t0 + 8) * DM + h * HDIM + cc) = v1;
        }
    }
}

// ---------------- launcher ----------------
extern "C" void kernel_launch(void* const* d_in, const int* in_sizes, int n_in,
                              void* d_out, int out_size)
{
    const float* x     = (const float*)d_in[0];
    const int*   amask = (const int*)  d_in[1];
    const float* ln1g  = (const float*)d_in[2];
    const float* ln1b  = (const float*)d_in[3];
    const float* Wqkv  = (const float*)d_in[4];
    const float* bqkv  = (const float*)d_in[5];
    const float* Wo    = (const float*)d_in[6];
    const float* bo    = (const float*)d_in[7];
    const float* ln2g  = (const float*)d_in[8];
    const float* ln2b  = (const float*)d_in[9];
    const float* W1    = (const float*)d_in[10];
    const float* b1    = (const float*)d_in[11];
    const float* W2    = (const float*)d_in[12];
    const float* b2    = (const float*)d_in[13];
    float* out = (float*)d_out;

    void *p_ln, *p_qkv, *p_y, *p_x2, *p_ff;
    cudaGetSymbolAddress(&p_ln,  g_ln);
    cudaGetSymbolAddress(&p_qkv, g_qkv);
    cudaGetSymbolAddress(&p_y,   g_y);
    cudaGetSymbolAddress(&p_x2,  g_x2);
    cudaGetSymbolAddress(&p_ff,  g_ff);

    cudaFuncSetAttribute(attn_kernel,
        cudaFuncAttributeMaxDynamicSharedMemorySize, ATTN_SMEM);

    // 1. LN1
    ln_kernel<<<T_SEQ, 256>>>(x, ln1g, ln1b, (float*)p_ln);
    // 2. QKV = h @ W_qkv + b
    gemm_tf32<0><<<dim3(24, 32), 256>>>((float*)p_ln, Wqkv, bqkv, nullptr,
                                        (float*)p_qkv, T_SEQ, 3 * DM, DM);
    // 3. causal attention
    attn_kernel<<<dim3(64, 16), 256, ATTN_SMEM>>>((float*)p_qkv, amask, (float*)p_y);
    // 4. x2 = x + y @ W_o + b_o
    gemm_tf32<1><<<dim3(8, 32), 256>>>((float*)p_y, Wo, bo, x,
                                       (float*)p_x2, T_SEQ, DM, DM);
    // 5. LN2
    ln_kernel<<<T_SEQ, 256>>>((float*)p_x2, ln2g, ln2b, (float*)p_ln);
    // 6. ff = gelu(h2 @ W1 + b1)
    gemm_tf32<2><<<dim3(32, 32), 256>>>((float*)p_ln, W1, b1, nullptr,
                                        (float*)p_ff, T_SEQ, DFF, DM);
    // 7. out = x2 + ff @ W2 + b2
    gemm_tf32<1><<<dim3(8, 32), 256>>>((float*)p_ff, W2, b2, (float*)p_x2,
                                       out, T_SEQ, DM, DFF);
}

// round 2
// speedup vs baseline: 1.0573x; 1.0573x over previous
#include <cuda_runtime.h>
#include <cstdint>
#include <math.h>

#define T_SEQ   4096
#define DM      1024
#define DFF     4096
#define NHEADS  16
#define HDIM    64
#define LN_EPS  1e-5f

// ---------------- scratch (static device globals; no allocation) ----------------
static __device__ float g_ln [T_SEQ * DM];        // 16 MB
static __device__ float g_qkv[T_SEQ * 3 * DM];    // 48 MB
static __device__ float g_y  [T_SEQ * DM];        // 16 MB
static __device__ float g_x2 [T_SEQ * DM];        // 16 MB
static __device__ float g_ff [T_SEQ * DFF];       // 64 MB

// ---------------- helpers ----------------
__device__ __forceinline__ float to_tf32(float x) {
    uint32_t u;
    asm("cvt.rna.tf32.f32 %0, %1;" : "=r"(u) : "f"(x));
    return __uint_as_float(u);
}
__device__ __forceinline__ uint32_t to_tf32_u(float x) {
    uint32_t u;
    asm("cvt.rna.tf32.f32 %0, %1;" : "=r"(u) : "f"(x));
    return u;
}

__device__ __forceinline__ void mma_tf32(float* c,
    uint32_t a0, uint32_t a1, uint32_t a2, uint32_t a3,
    uint32_t b0, uint32_t b1)
{
    asm volatile(
        "mma.sync.aligned.m16n8k8.row.col.f32.tf32.tf32.f32 "
        "{%0,%1,%2,%3}, {%4,%5,%6,%7}, {%8,%9}, {%0,%1,%2,%3};\n"
        : "+f"(c[0]), "+f"(c[1]), "+f"(c[2]), "+f"(c[3])
        : "r"(a0), "r"(a1), "r"(a2), "r"(a3), "r"(b0), "r"(b1));
}

__device__ __forceinline__ void cp16(uint32_t dst, const void* src) {
    asm volatile("cp.async.ca.shared.global [%0], [%1], 16;\n"
                 :: "r"(dst), "l"(src));
}

__device__ __forceinline__ float gelu_exact(float v) {
    return 0.5f * v * (1.0f + erff(v * 0.70710678118654752440f));
}

// ---------------- LayerNorm: one block per row of 1024 ----------------
__global__ __launch_bounds__(256) void ln_kernel(
    const float* __restrict__ x, const float* __restrict__ g,
    const float* __restrict__ b, float* __restrict__ out)
{
    int row = blockIdx.x;
    int tid = threadIdx.x;
    const float4 v = ((const float4*)(x + (size_t)row * DM))[tid];
    float s  = v.x + v.y + v.z + v.w;
    float sq = v.x * v.x + v.y * v.y + v.z * v.z + v.w * v.w;
    #pragma unroll
    for (int o = 16; o; o >>= 1) {
        s  += __shfl_xor_sync(0xffffffffu, s,  o);
        sq += __shfl_xor_sync(0xffffffffu, sq, o);
    }
    __shared__ float ss[8], ssq[8];
    __shared__ float mean_s, inv_s;
    int w = tid >> 5, l = tid & 31;
    if (l == 0) { ss[w] = s; ssq[w] = sq; }
    __syncthreads();
    if (tid == 0) {
        float st = 0.f, sqt = 0.f;
        #pragma unroll
        for (int i = 0; i < 8; i++) { st += ss[i]; sqt += ssq[i]; }
        float mean = st * (1.0f / DM);
        float var  = sqt * (1.0f / DM) - mean * mean;
        mean_s = mean;
        inv_s  = rsqrtf(var + LN_EPS);
    }
    __syncthreads();
    float mean = mean_s, inv = inv_s;
    const float4 gv = ((const float4*)g)[tid];
    const float4 bv = ((const float4*)b)[tid];
    float4 o;
    o.x = (v.x - mean) * inv * gv.x + bv.x;
    o.y = (v.y - mean) * inv * gv.y + bv.y;
    o.z = (v.z - mean) * inv * gv.z + bv.z;
    o.w = (v.w - mean) * inv * gv.w + bv.w;
    ((float4*)(out + (size_t)row * DM))[tid] = o;
}

// ---------------- TF32 GEMM (unchanged from passing version) ----------------
template<int MODE>
__global__ __launch_bounds__(256) void gemm_tf32(
    const float* __restrict__ A, const float* __restrict__ B,
    const float* __restrict__ bias, const float* __restrict__ res,
    float* __restrict__ C, int M, int N, int K)
{
    __shared__ float As[2][16][132];
    __shared__ float Bs[2][16][132];

    const int tid  = threadIdx.x;
    const int lane = tid & 31, w = tid >> 5;
    const int wm = w >> 2, wn = w & 3;
    const int gp = lane >> 2, tg = lane & 3;
    const int m0 = blockIdx.y * 128, n0 = blockIdx.x * 128;

    float c[4][4][4];
    #pragma unroll
    for (int i = 0; i < 4; i++)
        #pragma unroll
        for (int j = 0; j < 4; j++)
            #pragma unroll
            for (int r = 0; r < 4; r++) c[i][j][r] = 0.f;

    const int KT = K >> 4;
    float4 va[2], vb[2];

    #pragma unroll
    for (int i = 0; i < 2; i++) {
        int idx = tid + i * 256;
        int r = idx >> 2, c4 = (idx & 3) << 2;
        va[i] = *(const float4*)(A + (size_t)(m0 + r) * K + c4);
        int rb = idx >> 5, cb = (idx & 31) << 2;
        vb[i] = *(const float4*)(B + (size_t)rb * N + n0 + cb);
    }
    #pragma unroll
    for (int i = 0; i < 2; i++) {
        int idx = tid + i * 256;
        int r = idx >> 2, c4 = (idx & 3) << 2;
        As[0][c4 + 0][r] = to_tf32(va[i].x);
        As[0][c4 + 1][r] = to_tf32(va[i].y);
        As[0][c4 + 2][r] = to_tf32(va[i].z);
        As[0][c4 + 3][r] = to_tf32(va[i].w);
        int rb = idx >> 5, cb = (idx & 31) << 2;
        float4 t; t.x = to_tf32(vb[i].x); t.y = to_tf32(vb[i].y);
        t.z = to_tf32(vb[i].z); t.w = to_tf32(vb[i].w);
        *(float4*)&Bs[0][rb][cb] = t;
    }
    __syncthreads();

    int cur = 0;
    for (int kt = 0; kt < KT; kt++) {
        if (kt + 1 < KT) {
            #pragma unroll
            for (int i = 0; i < 2; i++) {
                int idx = tid + i * 256;
                int r = idx >> 2, c4 = (idx & 3) << 2;
                va[i] = *(const float4*)(A + (size_t)(m0 + r) * K + (kt + 1) * 16 + c4);
                int rb = idx >> 5, cb = (idx & 31) << 2;
                vb[i] = *(const float4*)(B + (size_t)((kt + 1) * 16 + rb) * N + n0 + cb);
            }
        }
        #pragma unroll
        for (int ks = 0; ks < 2; ks++) {
            const int k = ks * 8;
            uint32_t a[4][4], b[4][2];
            #pragma unroll
            for (int mf = 0; mf < 4; mf++) {
                int r0 = wm * 64 + mf * 16;
                a[mf][0] = __float_as_uint(As[cur][k + tg    ][r0 + gp    ]);
                a[mf][1] = __float_as_uint(As[cur][k + tg    ][r0 + gp + 8]);
                a[mf][2] = __float_as_uint(As[cur][k + tg + 4][r0 + gp    ]);
                a[mf][3] = __float_as_uint(As[cur][k + tg + 4][r0 + gp + 8]);
            }
            #pragma unroll
            for (int nf = 0; nf < 4; nf++) {
                int c0 = wn * 32 + nf * 8;
                b[nf][0] = __float_as_uint(Bs[cur][k + tg    ][c0 + gp]);
                b[nf][1] = __float_as_uint(Bs[cur][k + tg + 4][c0 + gp]);
            }
            #pragma unroll
            for (int mf = 0; mf < 4; mf++)
                #pragma unroll
                for (int nf = 0; nf < 4; nf++)
                    mma_tf32(c[mf][nf], a[mf][0], a[mf][1], a[mf][2], a[mf][3],
                             b[nf][0], b[nf][1]);
        }
        if (kt + 1 < KT) {
            int nxt = cur ^ 1;
            #pragma unroll
            for (int i = 0; i < 2; i++) {
                int idx = tid + i * 256;
                int r = idx >> 2, c4 = (idx & 3) << 2;
                As[nxt][c4 + 0][r] = to_tf32(va[i].x);
                As[nxt][c4 + 1][r] = to_tf32(va[i].y);
                As[nxt][c4 + 2][r] = to_tf32(va[i].z);
                As[nxt][c4 + 3][r] = to_tf32(va[i].w);
                int rb = idx >> 5, cb = (idx & 31) << 2;
                float4 t; t.x = to_tf32(vb[i].x); t.y = to_tf32(vb[i].y);
                t.z = to_tf32(vb[i].z); t.w = to_tf32(vb[i].w);
                *(float4*)&Bs[nxt][rb][cb] = t;
            }
            __syncthreads();
            cur = nxt;
        }
    }

    #pragma unroll
    for (int mf = 0; mf < 4; mf++) {
        #pragma unroll
        for (int nf = 0; nf < 4; nf++) {
            int col = n0 + wn * 32 + nf * 8 + 2 * tg;
            float bi0 = bias[col], bi1 = bias[col + 1];
            #pragma unroll
            for (int h = 0; h < 2; h++) {
                int row = m0 + wm * 64 + mf * 16 + gp + h * 8;
                float v0 = c[mf][nf][h * 2 + 0] + bi0;
                float v1 = c[mf][nf][h * 2 + 1] + bi1;
                if (MODE == 1) {
                    const float2 rv = *(const float2*)(res + (size_t)row * N + col);
                    v0 += rv.x; v1 += rv.y;
                }
                if (MODE == 2) { v0 = gelu_exact(v0); v1 = gelu_exact(v1); }
                float2 o; o.x = v0; o.y = v1;
                *(float2*)(C + (size_t)row * N + col) = o;
            }
        }
    }
}

// ---------------- causal flash attention v2 ----------------
// grid (32 qtiles, 16 heads), 256 threads (8 warps), 128-query x 64-key tiles.
// Warp w owns query rows [w*16, w*16+16). S, P, O register-resident.
// K/V double-buffered via cp.async, stride 76 (conflict-free B-frag LDS).
#define AT_STRIDE 76
#define AT_BUF    (64 * AT_STRIDE)
#define ATTN_SMEM ((4 * AT_BUF) * 4 + 2 * 64 * 4)

__global__ __launch_bounds__(256, 2) void attn_kernel(
    const float* __restrict__ qkv, const int* __restrict__ amask,
    float* __restrict__ y)
{
    extern __shared__ float sm[];
    float* kb = sm;                       // [2][64][76]
    float* vb = sm + 2 * AT_BUF;          // [2][64][76]
    int*   mk = (int*)(sm + 4 * AT_BUF);  // [2][64]

    const int tid = threadIdx.x, lane = tid & 31, w = tid >> 5;
    const int gp = lane >> 2, tg = lane & 3;
    const int h = blockIdx.y;
    const int q0 = blockIdx.x * 128;
    const int qw = q0 + w * 16;           // warp's first query row

    // ---- stage Q tile (128x64) into buffer-1 regions ----
    #pragma unroll
    for (int i = 0; i < 8; i++) {
        int idx = tid + i * 256;          // 0..2047
        int r = idx >> 4, c4 = (idx & 15) << 2;
        const float4 v = *(const float4*)(qkv + (size_t)(q0 + r) * (3 * DM) + h * HDIM + c4);
        float* dst = (r < 64 ? (kb + AT_BUF) : (vb + AT_BUF)) + (r & 63) * AT_STRIDE + c4;
        *(float4*)dst = v;
    }

    // ---- prefetch K/V tile 0 + mask into buffer 0 ----
    {
        int r = tid >> 2, cg = (tid & 3) << 4;
        const float* gk = qkv + (size_t)r * (3 * DM) + DM + h * HDIM + cg;
        uint32_t dk = (uint32_t)__cvta_generic_to_shared(kb + r * AT_STRIDE + cg);
        uint32_t dv = (uint32_t)__cvta_generic_to_shared(vb + r * AT_STRIDE + cg);
        #pragma unroll
        for (int i = 0; i < 4; i++) {
            cp16(dk + i * 16, gk + i * 4);
            cp16(dv + i * 16, gk + DM + i * 4);
        }
        if (tid < 16) {
            uint32_t dm = (uint32_t)__cvta_generic_to_shared(mk + tid * 4);
            cp16(dm, amask + tid * 4);
        }
    }
    asm volatile("cp.async.commit_group;\n" ::: "memory");
    __syncthreads();

    // ---- Q fragments into registers (RNA-rounded tf32) ----
    uint32_t qa[8][4];
    {
        const float* st = (w < 4 ? (kb + AT_BUF) : (vb + AT_BUF));
        int r0 = (w * 16) & 63;
        #pragma unroll
        for (int ks = 0; ks < 8; ks++) {
            qa[ks][0] = to_tf32_u(st[(r0 + gp    ) * AT_STRIDE + ks * 8 + tg    ]);
            qa[ks][1] = to_tf32_u(st[(r0 + gp + 8) * AT_STRIDE + ks * 8 + tg    ]);
            qa[ks][2] = to_tf32_u(st[(r0 + gp    ) * AT_STRIDE + ks * 8 + tg + 4]);
            qa[ks][3] = to_tf32_u(st[(r0 + gp + 8) * AT_STRIDE + ks * 8 + tg + 4]);
        }
    }

    float m0 = -INFINITY, m1 = -INFINITY, l0 = 0.f, l1 = 0.f;
    float o[8][4];
    #pragma unroll
    for (int nf = 0; nf < 8; nf++)
        #pragma unroll
        for (int r = 0; r < 4; r++) o[nf][r] = 0.f;

    const int ktmax = (q0 + 127) >> 6;
    const int row0 = qw + gp, row1 = qw + gp + 8;
    int cur = 0;

    for (int kt = 0; kt <= ktmax; kt++) {
        asm volatile("cp.async.wait_group 0;\n" ::: "memory");
        __syncthreads();

        if (kt < ktmax) {
            int nb = cur ^ 1;
            int r = tid >> 2, cg = (tid & 3) << 4;
            const float* gk = qkv + (size_t)((kt + 1) * 64 + r) * (3 * DM) + DM + h * HDIM + cg;
            uint32_t dk = (uint32_t)__cvta_generic_to_shared(kb + nb * AT_BUF + r * AT_STRIDE + cg);
            uint32_t dv = (uint32_t)__cvta_generic_to_shared(vb + nb * AT_BUF + r * AT_STRIDE + cg);
            #pragma unroll
            for (int i = 0; i < 4; i++) {
                cp16(dk + i * 16, gk + i * 4);
                cp16(dv + i * 16, gk + DM + i * 4);
            }
            if (tid < 16) {
                uint32_t dm = (uint32_t)__cvta_generic_to_shared(mk + nb * 64 + tid * 4);
                cp16(dm, amask + (kt + 1) * 64 + tid * 4);
            }
            asm volatile("cp.async.commit_group;\n" ::: "memory");
        }

        const float* K = kb + cur * AT_BUF;
        const float* V = vb + cur * AT_BUF;
        const int*   M = mk + cur * 64;

        // ---- S = Q @ K^T (16 x 64 per warp, register C) ----
        float sc[8][4];
        #pragma unroll
        for (int nf = 0; nf < 8; nf++)
            #pragma unroll
            for (int r = 0; r < 4; r++) sc[nf][r] = 0.f;

        #pragma unroll
        for (int ks = 0; ks < 8; ks++) {
            #pragma unroll
            for (int nf = 0; nf < 8; nf++) {
                uint32_t b0 = __float_as_uint(K[(nf * 8 + gp) * AT_STRIDE + ks * 8 + tg    ]);
                uint32_t b1 = __float_as_uint(K[(nf * 8 + gp) * AT_STRIDE + ks * 8 + tg + 4]);
                mma_tf32(sc[nf], qa[ks][0], qa[ks][1], qa[ks][2], qa[ks][3], b0, b1);
            }
        }

        // ---- mask + scale + online softmax (register) ----
        float tm0 = -INFINITY, tm1 = -INFINITY;
        #pragma unroll
        for (int nf = 0; nf < 8; nf++) {
            int cl = nf * 8 + 2 * tg;
            int c  = kt * 64 + cl;
            bool mk0 = M[cl] != 0, mk1 = M[cl + 1] != 0;
            float s0 = sc[nf][0] * 0.125f, s1 = sc[nf][1] * 0.125f;
            float s2 = sc[nf][2] * 0.125f, s3 = sc[nf][3] * 0.125f;
            s0 = (c     <= row0 && mk0) ? s0 : -INFINITY;
            s1 = (c + 1 <= row0 && mk1) ? s1 : -INFINITY;
            s2 = (c     <= row1 && mk0) ? s2 : -INFINITY;
            s3 = (c + 1 <= row1 && mk1) ? s3 : -INFINITY;
            sc[nf][0] = s0; sc[nf][1] = s1; sc[nf][2] = s2; sc[nf][3] = s3;
            tm0 = fmaxf(tm0, fmaxf(s0, s1));
            tm1 = fmaxf(tm1, fmaxf(s2, s3));
        }
        tm0 = fmaxf(tm0, __shfl_xor_sync(0xffffffffu, tm0, 1));
        tm0 = fmaxf(tm0, __shfl_xor_sync(0xffffffffu, tm0, 2));
        tm1 = fmaxf(tm1, __shfl_xor_sync(0xffffffffu, tm1, 1));
        tm1 = fmaxf(tm1, __shfl_xor_sync(0xffffffffu, tm1, 2));

        float nm0 = fmaxf(m0, tm0), nm1 = fmaxf(m1, tm1);
        float ne0 = fmaxf(nm0, -1e30f), ne1 = fmaxf(nm1, -1e30f);
        float al0 = __expf(m0 - ne0), al1 = __expf(m1 - ne1);
        m0 = nm0; m1 = nm1;

        float ps0 = 0.f, ps1 = 0.f;
        #pragma unroll
        for (int nf = 0; nf < 8; nf++) {
            float p0 = __expf(sc[nf][0] - ne0);
            float p1 = __expf(sc[nf][1] - ne0);
            float p2 = __expf(sc[nf][2] - ne1);
            float p3 = __expf(sc[nf][3] - ne1);
            sc[nf][0] = p0; sc[nf][1] = p1; sc[nf][2] = p2; sc[nf][3] = p3;
            ps0 += p0 + p1; ps1 += p2 + p3;
        }
        ps0 += __shfl_xor_sync(0xffffffffu, ps0, 1);
        ps0 += __shfl_xor_sync(0xffffffffu, ps0, 2);
        ps1 += __shfl_xor_sync(0xffffffffu, ps1, 1);
        ps1 += __shfl_xor_sync(0xffffffffu, ps1, 2);
        l0 = l0 * al0 + ps0;
        l1 = l1 * al1 + ps1;

        #pragma unroll
        for (int nf = 0; nf < 8; nf++) {
            o[nf][0] *= al0; o[nf][1] *= al0;
            o[nf][2] *= al1; o[nf][3] *= al1;
        }

        // ---- O += P @ V (quad-shuffle transpose of P into A-frags) ----
        const int src0 = (lane & ~3) | (tg >> 1);
        const int src1 = src0 + 2;
        const bool odd = (tg & 1) != 0;
        #pragma unroll
        for (int ks = 0; ks < 8; ks++) {
            float e00 = __shfl_sync(0xffffffffu, sc[ks][0], src0);
            float e01 = __shfl_sync(0xffffffffu, sc[ks][1], src0);
            float e10 = __shfl_sync(0xffffffffu, sc[ks][2], src0);
            float e11 = __shfl_sync(0xffffffffu, sc[ks][3], src0);
            float f00 = __shfl_sync(0xffffffffu, sc[ks][0], src1);
            float f01 = __shfl_sync(0xffffffffu, sc[ks][1], src1);
            float f10 = __shfl_sync(0xffffffffu, sc[ks][2], src1);
            float f11 = __shfl_sync(0xffffffffu, sc[ks][3], src1);
            uint32_t pa0 = to_tf32_u(odd ? e01 : e00);
            uint32_t pa1 = to_tf32_u(odd ? e11 : e10);
            uint32_t pa2 = to_tf32_u(odd ? f01 : f00);
            uint32_t pa3 = to_tf32_u(odd ? f11 : f10);
            #pragma unroll
            for (int nf = 0; nf < 8; nf++) {
                uint32_t b0 = __float_as_uint(V[(ks * 8 + tg    ) * AT_STRIDE + nf * 8 + gp]);
                uint32_t b1 = __float_as_uint(V[(ks * 8 + tg + 4) * AT_STRIDE + nf * 8 + gp]);
                mma_tf32(o[nf], pa0, pa1, pa2, pa3, b0, b1);
            }
        }
        cur ^= 1;
    }

    // ---- write out: y[t][h*64+d] = o / l ----
    float il0 = 1.0f / fmaxf(l0, 1e-30f);
    float il1 = 1.0f / fmaxf(l1, 1e-30f);
    #pragma unroll
    for (int nf = 0; nf < 8; nf++) {
        int col = h * HDIM + nf * 8 + 2 * tg;
        float2 v0; v0.x = o[nf][0] * il0; v0.y = o[nf][1] * il0;
        *(float2*)(y + (size_t)row0 * DM + col) = v0;
        float2 v1; v1.x = o[nf][2] * il1; v1.y = o[nf][3] * il1;
        *(float2*)(y + (size_t)row1 * DM + col) = v1;
    }
}

// ---------------- launcher ----------------
extern "C" void kernel_launch(void* const* d_in, const int* in_sizes, int n_in,
                              void* d_out, int out_size)
{
    const float* x     = (const float*)d_in[0];
    const int*   amask = (const int*)  d_in[1];
    const float* ln1g  = (const float*)d_in[2];
    const float* ln1b  = (const float*)d_in[3];
    const float* Wqkv  = (const float*)d_in[4];
    const float* bqkv  = (const float*)d_in[5];
    const float* Wo    = (const float*)d_in[6];
    const float* bo    = (const float*)d_in[7];
    const float* ln2g  = (const float*)d_in[8];
    const float* ln2b  = (const float*)d_in[9];
    const float* W1    = (const float*)d_in[10];
    const float* b1    = (const float*)d_in[11];
    const float* W2    = (const float*)d_in[12];
    const float* b2    = (const float*)d_in[13];
    float* out = (float*)d_out;

    void *p_ln, *p_qkv, *p_y, *p_x2, *p_ff;
    cudaGetSymbolAddress(&p_ln,  g_ln);
    cudaGetSymbolAddress(&p_qkv, g_qkv);
    cudaGetSymbolAddress(&p_y,   g_y);
    cudaGetSymbolAddress(&p_x2,  g_x2);
    cudaGetSymbolAddress(&p_ff,  g_ff);

    cudaFuncSetAttribute(attn_kernel,
        cudaFuncAttributeMaxDynamicSharedMemorySize, ATTN_SMEM);

    // 1. LN1
    ln_kernel<<<T_SEQ, 256>>>(x, ln1g, ln1b, (float*)p_ln);
    // 2. QKV = h @ W_qkv + b
    gemm_tf32<0><<<dim3(24, 32), 256>>>((float*)p_ln, Wqkv, bqkv, nullptr,
                                        (float*)p_qkv, T_SEQ, 3 * DM, DM);
    // 3. causal attention (FA2, register-resident)
    attn_kernel<<<dim3(32, 16), 256, ATTN_SMEM>>>((float*)p_qkv, amask, (float*)p_y);
    // 4. x2 = x + y @ W_o + b_o
    gemm_tf32<1><<<dim3(8, 32), 256>>>((float*)p_y, Wo, bo, x,
                                       (float*)p_x2, T_SEQ, DM, DM);
    // 5. LN2
    ln_kernel<<<T_SEQ, 256>>>((float*)p_x2, ln2g, ln2b, (float*)p_ln);
    // 6. ff = gelu(h2 @ W1 + b1)
    gemm_tf32<2><<<dim3(32, 32), 256>>>((float*)p_ln, W1, b1, nullptr,
                                        (float*)p_ff, T_SEQ, DFF, DM);
    // 7. out = x2 + ff @ W2 + b2
    gemm_tf32<1><<<dim3(8, 32), 256>>>((float*)p_ff, W2, b2, (float*)p_x2,
                                       out, T_SEQ, DM, DFF);
}

// round 3
// speedup vs baseline: 1.0635x; 1.0059x over previous
#include <cuda_runtime.h>
#include <cstdint>
#include <math.h>

#define T_SEQ   4096
#define DM      1024
#define DFF     4096
#define NHEADS  16
#define HDIM    64
#define LN_EPS  1e-5f

// ---------------- scratch (static device globals; no allocation) ----------------
static __device__ float g_ln [T_SEQ * DM];        // 16 MB
static __device__ float g_qkv[T_SEQ * 3 * DM];    // 48 MB
static __device__ float g_y  [T_SEQ * DM];        // 16 MB
static __device__ float g_x2 [T_SEQ * DM];        // 16 MB
static __device__ float g_ff [T_SEQ * DFF];       // 64 MB

// ---------------- helpers ----------------
__device__ __forceinline__ float to_tf32(float x) {
    uint32_t u;
    asm("cvt.rna.tf32.f32 %0, %1;" : "=r"(u) : "f"(x));
    return __uint_as_float(u);
}
__device__ __forceinline__ uint32_t to_tf32_u(float x) {
    uint32_t u;
    asm("cvt.rna.tf32.f32 %0, %1;" : "=r"(u) : "f"(x));
    return u;
}

__device__ __forceinline__ void mma_tf32(float* c,
    uint32_t a0, uint32_t a1, uint32_t a2, uint32_t a3,
    uint32_t b0, uint32_t b1)
{
    asm volatile(
        "mma.sync.aligned.m16n8k8.row.col.f32.tf32.tf32.f32 "
        "{%0,%1,%2,%3}, {%4,%5,%6,%7}, {%8,%9}, {%0,%1,%2,%3};\n"
        : "+f"(c[0]), "+f"(c[1]), "+f"(c[2]), "+f"(c[3])
        : "r"(a0), "r"(a1), "r"(a2), "r"(a3), "r"(b0), "r"(b1));
}

__device__ __forceinline__ void cp16(uint32_t dst, const void* src) {
    asm volatile("cp.async.ca.shared.global [%0], [%1], 16;\n"
                 :: "r"(dst), "l"(src));
}

__device__ __forceinline__ float gelu_exact(float v) {
    return 0.5f * v * (1.0f + erff(v * 0.70710678118654752440f));
}

// ---------------- LayerNorm: one block per row of 1024 ----------------
__global__ __launch_bounds__(256) void ln_kernel(
    const float* __restrict__ x, const float* __restrict__ g,
    const float* __restrict__ b, float* __restrict__ out)
{
    int row = blockIdx.x;
    int tid = threadIdx.x;
    const float4 v = ((const float4*)(x + (size_t)row * DM))[tid];
    float s  = v.x + v.y + v.z + v.w;
    float sq = v.x * v.x + v.y * v.y + v.z * v.z + v.w * v.w;
    #pragma unroll
    for (int o = 16; o; o >>= 1) {
        s  += __shfl_xor_sync(0xffffffffu, s,  o);
        sq += __shfl_xor_sync(0xffffffffu, sq, o);
    }
    __shared__ float ss[8], ssq[8];
    __shared__ float mean_s, inv_s;
    int w = tid >> 5, l = tid & 31;
    if (l == 0) { ss[w] = s; ssq[w] = sq; }
    __syncthreads();
    if (tid == 0) {
        float st = 0.f, sqt = 0.f;
        #pragma unroll
        for (int i = 0; i < 8; i++) { st += ss[i]; sqt += ssq[i]; }
        float mean = st * (1.0f / DM);
        float var  = sqt * (1.0f / DM) - mean * mean;
        mean_s = mean;
        inv_s  = rsqrtf(var + LN_EPS);
    }
    __syncthreads();
    float mean = mean_s, inv = inv_s;
    const float4 gv = ((const float4*)g)[tid];
    const float4 bv = ((const float4*)b)[tid];
    float4 o;
    o.x = (v.x - mean) * inv * gv.x + bv.x;
    o.y = (v.y - mean) * inv * gv.y + bv.y;
    o.z = (v.z - mean) * inv * gv.z + bv.z;
    o.w = (v.w - mean) * inv * gv.w + bv.w;
    ((float4*)(out + (size_t)row * DM))[tid] = o;
}

// ---------------- TF32 GEMM (unchanged from passing version) ----------------
template<int MODE>
__global__ __launch_bounds__(256) void gemm_tf32(
    const float* __restrict__ A, const float* __restrict__ B,
    const float* __restrict__ bias, const float* __restrict__ res,
    float* __restrict__ C, int M, int N, int K)
{
    __shared__ float As[2][16][132];
    __shared__ float Bs[2][16][132];

    const int tid  = threadIdx.x;
    const int lane = tid & 31, w = tid >> 5;
    const int wm = w >> 2, wn = w & 3;
    const int gp = lane >> 2, tg = lane & 3;
    const int m0 = blockIdx.y * 128, n0 = blockIdx.x * 128;

    float c[4][4][4];
    #pragma unroll
    for (int i = 0; i < 4; i++)
        #pragma unroll
        for (int j = 0; j < 4; j++)
            #pragma unroll
            for (int r = 0; r < 4; r++) c[i][j][r] = 0.f;

    const int KT = K >> 4;
    float4 va[2], vb[2];

    #pragma unroll
    for (int i = 0; i < 2; i++) {
        int idx = tid + i * 256;
        int r = idx >> 2, c4 = (idx & 3) << 2;
        va[i] = *(const float4*)(A + (size_t)(m0 + r) * K + c4);
        int rb = idx >> 5, cb = (idx & 31) << 2;
        vb[i] = *(const float4*)(B + (size_t)rb * N + n0 + cb);
    }
    #pragma unroll
    for (int i = 0; i < 2; i++) {
        int idx = tid + i * 256;
        int r = idx >> 2, c4 = (idx & 3) << 2;
        As[0][c4 + 0][r] = to_tf32(va[i].x);
        As[0][c4 + 1][r] = to_tf32(va[i].y);
        As[0][c4 + 2][r] = to_tf32(va[i].z);
        As[0][c4 + 3][r] = to_tf32(va[i].w);
        int rb = idx >> 5, cb = (idx & 31) << 2;
        float4 t; t.x = to_tf32(vb[i].x); t.y = to_tf32(vb[i].y);
        t.z = to_tf32(vb[i].z); t.w = to_tf32(vb[i].w);
        *(float4*)&Bs[0][rb][cb] = t;
    }
    __syncthreads();

    int cur = 0;
    for (int kt = 0; kt < KT; kt++) {
        if (kt + 1 < KT) {
            #pragma unroll
            for (int i = 0; i < 2; i++) {
                int idx = tid + i * 256;
                int r = idx >> 2, c4 = (idx & 3) << 2;
                va[i] = *(const float4*)(A + (size_t)(m0 + r) * K + (kt + 1) * 16 + c4);
                int rb = idx >> 5, cb = (idx & 31) << 2;
                vb[i] = *(const float4*)(B + (size_t)((kt + 1) * 16 + rb) * N + n0 + cb);
            }
        }
        #pragma unroll
        for (int ks = 0; ks < 2; ks++) {
            const int k = ks * 8;
            uint32_t a[4][4], b[4][2];
            #pragma unroll
            for (int mf = 0; mf < 4; mf++) {
                int r0 = wm * 64 + mf * 16;
                a[mf][0] = __float_as_uint(As[cur][k + tg    ][r0 + gp    ]);
                a[mf][1] = __float_as_uint(As[cur][k + tg    ][r0 + gp + 8]);
                a[mf][2] = __float_as_uint(As[cur][k + tg + 4][r0 + gp    ]);
                a[mf][3] = __float_as_uint(As[cur][k + tg + 4][r0 + gp + 8]);
            }
            #pragma unroll
            for (int nf = 0; nf < 4; nf++) {
                int c0 = wn * 32 + nf * 8;
                b[nf][0] = __float_as_uint(Bs[cur][k + tg    ][c0 + gp]);
                b[nf][1] = __float_as_uint(Bs[cur][k + tg + 4][c0 + gp]);
            }
            #pragma unroll
            for (int mf = 0; mf < 4; mf++)
                #pragma unroll
                for (int nf = 0; nf < 4; nf++)
                    mma_tf32(c[mf][nf], a[mf][0], a[mf][1], a[mf][2], a[mf][3],
                             b[nf][0], b[nf][1]);
        }
        if (kt + 1 < KT) {
            int nxt = cur ^ 1;
            #pragma unroll
            for (int i = 0; i < 2; i++) {
                int idx = tid + i * 256;
                int r = idx >> 2, c4 = (idx & 3) << 2;
                As[nxt][c4 + 0][r] = to_tf32(va[i].x);
                As[nxt][c4 + 1][r] = to_tf32(va[i].y);
                As[nxt][c4 + 2][r] = to_tf32(va[i].z);
                As[nxt][c4 + 3][r] = to_tf32(va[i].w);
                int rb = idx >> 5, cb = (idx & 31) << 2;
                float4 t; t.x = to_tf32(vb[i].x); t.y = to_tf32(vb[i].y);
                t.z = to_tf32(vb[i].z); t.w = to_tf32(vb[i].w);
                *(float4*)&Bs[nxt][rb][cb] = t;
            }
            __syncthreads();
            cur = nxt;
        }
    }

    #pragma unroll
    for (int mf = 0; mf < 4; mf++) {
        #pragma unroll
        for (int nf = 0; nf < 4; nf++) {
            int col = n0 + wn * 32 + nf * 8 + 2 * tg;
            float bi0 = bias[col], bi1 = bias[col + 1];
            #pragma unroll
            for (int h = 0; h < 2; h++) {
                int row = m0 + wm * 64 + mf * 16 + gp + h * 8;
                float v0 = c[mf][nf][h * 2 + 0] + bi0;
                float v1 = c[mf][nf][h * 2 + 1] + bi1;
                if (MODE == 1) {
                    const float2 rv = *(const float2*)(res + (size_t)row * N + col);
                    v0 += rv.x; v1 += rv.y;
                }
                if (MODE == 2) { v0 = gelu_exact(v0); v1 = gelu_exact(v1); }
                float2 o; o.x = v0; o.y = v1;
                *(float2*)(C + (size_t)row * N + col) = o;
            }
        }
    }
}

// ---------------- causal flash attention v2 ----------------
// grid (32 qtiles, 16 heads), 256 threads (8 warps), 128-query x 64-key tiles.
// Warp w owns query rows [w*16, w*16+16). S, P, O register-resident.
// K/V double-buffered via cp.async, stride 76 (conflict-free B-frag LDS).
// NOTE: no minBlocks hint — 128-reg cap caused local-memory spills of S/P/O.
#define AT_STRIDE 76
#define AT_BUF    (64 * AT_STRIDE)
#define ATTN_SMEM ((4 * AT_BUF) * 4 + 2 * 64 * 4)

__global__ __launch_bounds__(256) void attn_kernel(
    const float* __restrict__ qkv, const int* __restrict__ amask,
    float* __restrict__ y)
{
    extern __shared__ float sm[];
    float* kb = sm;                       // [2][64][76]
    float* vb = sm + 2 * AT_BUF;          // [2][64][76]
    int*   mk = (int*)(sm + 4 * AT_BUF);  // [2][64]

    const int tid = threadIdx.x, lane = tid & 31, w = tid >> 5;
    const int gp = lane >> 2, tg = lane & 3;
    const int h = blockIdx.y;
    const int q0 = (gridDim.x - 1 - blockIdx.x) * 128;  // longest blocks first
    const int qw = q0 + w * 16;           // warp's first query row

    // ---- stage Q tile (128x64) into buffer-1 regions ----
    #pragma unroll
    for (int i = 0; i < 8; i++) {
        int idx = tid + i * 256;          // 0..2047
        int r = idx >> 4, c4 = (idx & 15) << 2;
        const float4 v = *(const float4*)(qkv + (size_t)(q0 + r) * (3 * DM) + h * HDIM + c4);
        float* dst = (r < 64 ? (kb + AT_BUF) : (vb + AT_BUF)) + (r & 63) * AT_STRIDE + c4;
        *(float4*)dst = v;
    }

    // ---- prefetch K/V tile 0 + mask into buffer 0 ----
    {
        int r = tid >> 2, cg = (tid & 3) << 4;
        const float* gk = qkv + (size_t)r * (3 * DM) + DM + h * HDIM + cg;
        uint32_t dk = (uint32_t)__cvta_generic_to_shared(kb + r * AT_STRIDE + cg);
        uint32_t dv = (uint32_t)__cvta_generic_to_shared(vb + r * AT_STRIDE + cg);
        #pragma unroll
        for (int i = 0; i < 4; i++) {
            cp16(dk + i * 16, gk + i * 4);
            cp16(dv + i * 16, gk + DM + i * 4);
        }
        if (tid < 16) {
            uint32_t dm = (uint32_t)__cvta_generic_to_shared(mk + tid * 4);
            cp16(dm, amask + tid * 4);
        }
    }
    asm volatile("cp.async.commit_group;\n" ::: "memory");
    __syncthreads();

    // ---- Q fragments into registers (RNA-rounded tf32) ----
    uint32_t qa[8][4];
    {
        const float* st = (w < 4 ? (kb + AT_BUF) : (vb + AT_BUF));
        int r0 = (w * 16) & 63;
        #pragma unroll
        for (int ks = 0; ks < 8; ks++) {
            qa[ks][0] = to_tf32_u(st[(r0 + gp    ) * AT_STRIDE + ks * 8 + tg    ]);
            qa[ks][1] = to_tf32_u(st[(r0 + gp + 8) * AT_STRIDE + ks * 8 + tg    ]);
            qa[ks][2] = to_tf32_u(st[(r0 + gp    ) * AT_STRIDE + ks * 8 + tg + 4]);
            qa[ks][3] = to_tf32_u(st[(r0 + gp + 8) * AT_STRIDE + ks * 8 + tg + 4]);
        }
    }

    float m0 = -INFINITY, m1 = -INFINITY, l0 = 0.f, l1 = 0.f;
    float o[8][4];
    #pragma unroll
    for (int nf = 0; nf < 8; nf++)
        #pragma unroll
        for (int r = 0; r < 4; r++) o[nf][r] = 0.f;

    const int ktmax = (q0 + 127) >> 6;
    const int row0 = qw + gp, row1 = qw + gp + 8;
    int cur = 0;

    for (int kt = 0; kt <= ktmax; kt++) {
        asm volatile("cp.async.wait_group 0;\n" ::: "memory");
        __syncthreads();

        if (kt < ktmax) {
            int nb = cur ^ 1;
            int r = tid >> 2, cg = (tid & 3) << 4;
            const float* gk = qkv + (size_t)((kt + 1) * 64 + r) * (3 * DM) + DM + h * HDIM + cg;
            uint32_t dk = (uint32_t)__cvta_generic_to_shared(kb + nb * AT_BUF + r * AT_STRIDE + cg);
            uint32_t dv = (uint32_t)__cvta_generic_to_shared(vb + nb * AT_BUF + r * AT_STRIDE + cg);
            #pragma unroll
            for (int i = 0; i < 4; i++) {
                cp16(dk + i * 16, gk + i * 4);
                cp16(dv + i * 16, gk + DM + i * 4);
            }
            if (tid < 16) {
                uint32_t dm = (uint32_t)__cvta_generic_to_shared(mk + nb * 64 + tid * 4);
                cp16(dm, amask + (kt + 1) * 64 + tid * 4);
            }
            asm volatile("cp.async.commit_group;\n" ::: "memory");
        }

        const float* K = kb + cur * AT_BUF;
        const float* V = vb + cur * AT_BUF;
        const int*   M = mk + cur * 64;

        // ---- S = Q @ K^T (16 x 64 per warp, register C) ----
        float sc[8][4];
        #pragma unroll
        for (int nf = 0; nf < 8; nf++)
            #pragma unroll
            for (int r = 0; r < 4; r++) sc[nf][r] = 0.f;

        #pragma unroll
        for (int ks = 0; ks < 8; ks++) {
            #pragma unroll
            for (int nf = 0; nf < 8; nf++) {
                uint32_t b0 = __float_as_uint(K[(nf * 8 + gp) * AT_STRIDE + ks * 8 + tg    ]);
                uint32_t b1 = __float_as_uint(K[(nf * 8 + gp) * AT_STRIDE + ks * 8 + tg + 4]);
                mma_tf32(sc[nf], qa[ks][0], qa[ks][1], qa[ks][2], qa[ks][3], b0, b1);
            }
        }

        // ---- mask + scale + online softmax (register) ----
        float tm0 = -INFINITY, tm1 = -INFINITY;
        #pragma unroll
        for (int nf = 0; nf < 8; nf++) {
            int cl = nf * 8 + 2 * tg;
            int c  = kt * 64 + cl;
            bool mk0 = M[cl] != 0, mk1 = M[cl + 1] != 0;
            float s0 = sc[nf][0] * 0.125f, s1 = sc[nf][1] * 0.125f;
            float s2 = sc[nf][2] * 0.125f, s3 = sc[nf][3] * 0.125f;
            s0 = (c     <= row0 && mk0) ? s0 : -INFINITY;
            s1 = (c + 1 <= row0 && mk1) ? s1 : -INFINITY;
            s2 = (c     <= row1 && mk0) ? s2 : -INFINITY;
            s3 = (c + 1 <= row1 && mk1) ? s3 : -INFINITY;
            sc[nf][0] = s0; sc[nf][1] = s1; sc[nf][2] = s2; sc[nf][3] = s3;
            tm0 = fmaxf(tm0, fmaxf(s0, s1));
            tm1 = fmaxf(tm1, fmaxf(s2, s3));
        }
        tm0 = fmaxf(tm0, __shfl_xor_sync(0xffffffffu, tm0, 1));
        tm0 = fmaxf(tm0, __shfl_xor_sync(0xffffffffu, tm0, 2));
        tm1 = fmaxf(tm1, __shfl_xor_sync(0xffffffffu, tm1, 1));
        tm1 = fmaxf(tm1, __shfl_xor_sync(0xffffffffu, tm1, 2));

        float nm0 = fmaxf(m0, tm0), nm1 = fmaxf(m1, tm1);
        float ne0 = fmaxf(nm0, -1e30f), ne1 = fmaxf(nm1, -1e30f);
        float al0 = __expf(m0 - ne0), al1 = __expf(m1 - ne1);
        m0 = nm0; m1 = nm1;

        float ps0 = 0.f, ps1 = 0.f;
        #pragma unroll
        for (int nf = 0; nf < 8; nf++) {
            float p0 = __expf(sc[nf][0] - ne0);
            float p1 = __expf(sc[nf][1] - ne0);
            float p2 = __expf(sc[nf][2] - ne1);
            float p3 = __expf(sc[nf][3] - ne1);
            sc[nf][0] = p0; sc[nf][1] = p1; sc[nf][2] = p2; sc[nf][3] = p3;
            ps0 += p0 + p1; ps1 += p2 + p3;
        }
        ps0 += __shfl_xor_sync(0xffffffffu, ps0, 1);
        ps0 += __shfl_xor_sync(0xffffffffu, ps0, 2);
        ps1 += __shfl_xor_sync(0xffffffffu, ps1, 1);
        ps1 += __shfl_xor_sync(0xffffffffu, ps1, 2);
        l0 = l0 * al0 + ps0;
        l1 = l1 * al1 + ps1;

        #pragma unroll
        for (int nf = 0; nf < 8; nf++) {
            o[nf][0] *= al0; o[nf][1] *= al0;
            o[nf][2] *= al1; o[nf][3] *= al1;
        }

        // ---- O += P @ V (quad-shuffle transpose of P into A-frags) ----
        const int src0 = (lane & ~3) | (tg >> 1);
        const int src1 = src0 + 2;
        const bool odd = (tg & 1) != 0;
        #pragma unroll
        for (int ks = 0; ks < 8; ks++) {
            float e00 = __shfl_sync(0xffffffffu, sc[ks][0], src0);
            float e01 = __shfl_sync(0xffffffffu, sc[ks][1], src0);
            float e10 = __shfl_sync(0xffffffffu, sc[ks][2], src0);
            float e11 = __shfl_sync(0xffffffffu, sc[ks][3], src0);
            float f00 = __shfl_sync(0xffffffffu, sc[ks][0], src1);
            float f01 = __shfl_sync(0xffffffffu, sc[ks][1], src1);
            float f10 = __shfl_sync(0xffffffffu, sc[ks][2], src1);
            float f11 = __shfl_sync(0xffffffffu, sc[ks][3], src1);
            uint32_t pa0 = to_tf32_u(odd ? e01 : e00);
            uint32_t pa1 = to_tf32_u(odd ? e11 : e10);
            uint32_t pa2 = to_tf32_u(odd ? f01 : f00);
            uint32_t pa3 = to_tf32_u(odd ? f11 : f10);
            #pragma unroll
            for (int nf = 0; nf < 8; nf++) {
                uint32_t b0 = __float_as_uint(V[(ks * 8 + tg    ) * AT_STRIDE + nf * 8 + gp]);
                uint32_t b1 = __float_as_uint(V[(ks * 8 + tg + 4) * AT_STRIDE + nf * 8 + gp]);
                mma_tf32(o[nf], pa0, pa1, pa2, pa3, b0, b1);
            }
        }
        cur ^= 1;
    }

    // ---- write out: y[t][h*64+d] = o / l ----
    float il0 = 1.0f / fmaxf(l0, 1e-30f);
    float il1 = 1.0f / fmaxf(l1, 1e-30f);
    #pragma unroll
    for (int nf = 0; nf < 8; nf++) {
        int col = h * HDIM + nf * 8 + 2 * tg;
        float2 v0; v0.x = o[nf][0] * il0; v0.y = o[nf][1] * il0;
        *(float2*)(y + (size_t)row0 * DM + col) = v0;
        float2 v1; v1.x = o[nf][2] * il1; v1.y = o[nf][3] * il1;
        *(float2*)(y + (size_t)row1 * DM + col) = v1;
    }
}

// ---------------- launcher ----------------
extern "C" void kernel_launch(void* const* d_in, const int* in_sizes, int n_in,
                              void* d_out, int out_size)
{
    const float* x     = (const float*)d_in[0];
    const int*   amask = (const int*)  d_in[1];
    const float* ln1g  = (const float*)d_in[2];
    const float* ln1b  = (const float*)d_in[3];
    const float* Wqkv  = (const float*)d_in[4];
    const float* bqkv  = (const float*)d_in[5];
    const float* Wo    = (const float*)d_in[6];
    const float* bo    = (const float*)d_in[7];
    const float* ln2g  = (const float*)d_in[8];
    const float* ln2b  = (const float*)d_in[9];
    const float* W1    = (const float*)d_in[10];
    const float* b1    = (const float*)d_in[11];
    const float* W2    = (const float*)d_in[12];
    const float* b2    = (const float*)d_in[13];
    float* out = (float*)d_out;

    void *p_ln, *p_qkv, *p_y, *p_x2, *p_ff;
    cudaGetSymbolAddress(&p_ln,  g_ln);
    cudaGetSymbolAddress(&p_qkv, g_qkv);
    cudaGetSymbolAddress(&p_y,   g_y);
    cudaGetSymbolAddress(&p_x2,  g_x2);
    cudaGetSymbolAddress(&p_ff,  g_ff);

    cudaFuncSetAttribute(attn_kernel,
        cudaFuncAttributeMaxDynamicSharedMemorySize, ATTN_SMEM);

    // 1. LN1
    ln_kernel<<<T_SEQ, 256>>>(x, ln1g, ln1b, (float*)p_ln);
    // 2. QKV = h @ W_qkv + b
    gemm_tf32<0><<<dim3(24, 32), 256>>>((float*)p_ln, Wqkv, bqkv, nullptr,
                                        (float*)p_qkv, T_SEQ, 3 * DM, DM);
    // 3. causal attention (FA2, register-resident)
    attn_kernel<<<dim3(32, 16), 256, ATTN_SMEM>>>((float*)p_qkv, amask, (float*)p_y);
    // 4. x2 = x + y @ W_o + b_o
    gemm_tf32<1><<<dim3(8, 32), 256>>>((float*)p_y, Wo, bo, x,
                                       (float*)p_x2, T_SEQ, DM, DM);
    // 5. LN2
    ln_kernel<<<T_SEQ, 256>>>((float*)p_x2, ln2g, ln2b, (float*)p_ln);
    // 6. ff = gelu(h2 @ W1 + b1)
    gemm_tf32<2><<<dim3(32, 32), 256>>>((float*)p_ln, W1, b1, nullptr,
                                        (float*)p_ff, T_SEQ, DFF, DM);
    // 7. out = x2 + ff @ W2 + b2
    gemm_tf32<1><<<dim3(8, 32), 256>>>((float*)p_ff, W2, b2, (float*)p_x2,
                                       out, T_SEQ, DM, DFF);
}

// round 5
// speedup vs baseline: 1.8011x; 1.6935x over previous
#include <cuda_runtime.h>
#include <cstdint>
#include <math.h>

#define T_SEQ   4096
#define DM      1024
#define DFF     4096
#define NHEADS  16
#define HDIM    64
#define LN_EPS  1e-5f

// ---- arch-specific feature gate: tcgen05 only exists on sm_10xa/f targets ----
#if defined(__CUDA_ARCH__)
#  if defined(__CUDA_ARCH_FEAT_SM103_ALL) || defined(__CUDA_ARCH_FEAT_SM100_ALL) || defined(__CUDA_ARCH_FEAT_SM101_ALL)
#    define GEMM_TC 1
#  elif defined(__CUDA_ARCH_SPECIFIC__)
#    define GEMM_TC ((__CUDA_ARCH_SPECIFIC__ >= 1000) ? 1 : 0)
#  elif defined(__CUDA_ARCH_FAMILY_SPECIFIC__)
#    define GEMM_TC ((__CUDA_ARCH_FAMILY_SPECIFIC__ >= 1000) ? 1 : 0)
#  else
#    define GEMM_TC 0
#  endif
#else
#  define GEMM_TC 0
#endif

// ---------------- scratch (static device globals; no allocation) ----------------
static __device__ float g_ln [T_SEQ * DM];
static __device__ float g_qkv[T_SEQ * 3 * DM];
static __device__ float g_y  [T_SEQ * DM];
static __device__ float g_x2 [T_SEQ * DM];
static __device__ float g_ff [T_SEQ * DFF];
// transposed (tf32-rounded) weights, [N, K] K-major
static __device__ float g_wt_qkv[3 * DM * DM];
static __device__ float g_wt_o  [DM * DM];
static __device__ float g_wt_1  [DFF * DM];
static __device__ float g_wt_2  [DM * DFF];

// ---------------- helpers ----------------
__device__ __forceinline__ float to_tf32(float x) {
    uint32_t u;
    asm("cvt.rna.tf32.f32 %0, %1;" : "=r"(u) : "f"(x));
    return __uint_as_float(u);
}
__device__ __forceinline__ uint32_t to_tf32_u(float x) {
    uint32_t u;
    asm("cvt.rna.tf32.f32 %0, %1;" : "=r"(u) : "f"(x));
    return u;
}

__device__ __forceinline__ void mma_tf32(float* c,
    uint32_t a0, uint32_t a1, uint32_t a2, uint32_t a3,
    uint32_t b0, uint32_t b1)
{
    asm volatile(
        "mma.sync.aligned.m16n8k8.row.col.f32.tf32.tf32.f32 "
        "{%0,%1,%2,%3}, {%4,%5,%6,%7}, {%8,%9}, {%0,%1,%2,%3};\n"
        : "+f"(c[0]), "+f"(c[1]), "+f"(c[2]), "+f"(c[3])
        : "r"(a0), "r"(a1), "r"(a2), "r"(a3), "r"(b0), "r"(b1));
}

__device__ __forceinline__ void cp16(uint32_t dst, const void* src) {
    asm volatile("cp.async.ca.shared.global [%0], [%1], 16;\n"
                 :: "r"(dst), "l"(src));
}

__device__ __forceinline__ float gelu_exact(float v) {
    return 0.5f * v * (1.0f + erff(v * 0.70710678118654752440f));
}

// ---------------- weight transpose + tf32 round:  out[n][k] = rn(in[k][n]) ----------------
__global__ __launch_bounds__(256) void transpose_kernel(
    const float* __restrict__ in, float* __restrict__ out, int R, int C)
{
    __shared__ float t[32][33];
    int bx = blockIdx.x * 32, by = blockIdx.y * 32;
    int x = threadIdx.x & 31, y = threadIdx.x >> 5;
    #pragma unroll
    for (int i = 0; i < 32; i += 8)
        t[y + i][x] = in[(size_t)(by + y + i) * C + bx + x];
    __syncthreads();
    #pragma unroll
    for (int i = 0; i < 32; i += 8)
        out[(size_t)(bx + y + i) * R + by + x] = to_tf32(t[x][y + i]);
}

// ---------------- LayerNorm (writes tf32-rounded output) ----------------
__global__ __launch_bounds__(256) void ln_kernel(
    const float* __restrict__ x, const float* __restrict__ g,
    const float* __restrict__ b, float* __restrict__ out)
{
    int row = blockIdx.x;
    int tid = threadIdx.x;
    const float4 v = ((const float4*)(x + (size_t)row * DM))[tid];
    float s  = v.x + v.y + v.z + v.w;
    float sq = v.x * v.x + v.y * v.y + v.z * v.z + v.w * v.w;
    #pragma unroll
    for (int o = 16; o; o >>= 1) {
        s  += __shfl_xor_sync(0xffffffffu, s,  o);
        sq += __shfl_xor_sync(0xffffffffu, sq, o);
    }
    __shared__ float ss[8], ssq[8];
    __shared__ float mean_s, inv_s;
    int w = tid >> 5, l = tid & 31;
    if (l == 0) { ss[w] = s; ssq[w] = sq; }
    __syncthreads();
    if (tid == 0) {
        float st = 0.f, sqt = 0.f;
        #pragma unroll
        for (int i = 0; i < 8; i++) { st += ss[i]; sqt += ssq[i]; }
        float mean = st * (1.0f / DM);
        float var  = sqt * (1.0f / DM) - mean * mean;
        mean_s = mean;
        inv_s  = rsqrtf(var + LN_EPS);
    }
    __syncthreads();
    float mean = mean_s, inv = inv_s;
    const float4 gv = ((const float4*)g)[tid];
    const float4 bv = ((const float4*)b)[tid];
    float4 o;
    o.x = to_tf32((v.x - mean) * inv * gv.x + bv.x);
    o.y = to_tf32((v.y - mean) * inv * gv.y + bv.y);
    o.z = to_tf32((v.z - mean) * inv * gv.z + bv.z);
    o.w = to_tf32((v.w - mean) * inv * gv.w + bv.w);
    ((float4*)(out + (size_t)row * DM))[tid] = o;
}

// ---------------- unified GEMM: C[M,N] = A[M,K] @ Bt[N,K]^T + epilogue --------
// Tile 128x128, 256 threads. grid = (N/128, M/128).
// TC path (sm_10xa/f): tcgen05 SS tf32, BK=32, 3-stage cp.async ring.
// Fallback (plain targets): proven mma.sync m16n8k8 tf32, BK=16, double-buffered.
// MODE 0: +bias, round tf32   MODE 1: +bias+res (fp32)   MODE 2: gelu(+bias), round
#define GS      3
#define G_TILE  16384
#define G_STAGE (2 * G_TILE)
#define G_BASE  1024
#define G_SMEM  (G_BASE + GS * G_STAGE)   // 99328

#if GEMM_TC
__device__ __forceinline__ bool elect_one() {
    uint32_t pred;
    asm volatile(
        "{\n\t.reg .pred p;\n\t"
        "elect.sync _|p, 0xFFFFFFFF;\n\t"
        "selp.b32 %0, 1, 0, p;\n\t}"
        : "=r"(pred));
    return pred != 0;
}
__device__ __forceinline__ uint64_t make_desc(uint32_t addr) {
    const uint64_t base = (2ULL << 61) | (1ULL << 46) | (64ULL << 32) | (1ULL << 16);
    return base | ((uint64_t)(addr >> 4) & 0x3FFF);
}
__device__ __forceinline__ void tc_mma_tf32_ss(uint32_t d, uint64_t ad, uint64_t bd,
                                               uint32_t idesc, bool acc)
{
    uint32_t en = acc ? 1u : 0u;
    asm volatile(
        "{\n\t.reg .pred p;\n\t"
        "setp.ne.u32 p, %4, 0;\n\t"
        "tcgen05.mma.cta_group::1.kind::tf32 [%0], %1, %2, %3, {%5, %5, %5, %5}, p;\n\t}"
        :: "r"(d), "l"(ad), "l"(bd), "r"(idesc), "r"(en), "r"(0u)
        : "memory");
}
#define MBAR_INIT(a, c) \
    asm volatile("mbarrier.init.shared.b64 [%0], %1;" :: "r"(a), "r"(c) : "memory")
#define MBAR_WAIT(a, par) do { \
    uint32_t _m = (a), _p = (par), _d; \
    asm volatile("{\n\t.reg .pred p;\n\t" \
        "mbarrier.try_wait.parity.acquire.cta.shared::cta.b64 p, [%1], %2;\n\t" \
        "selp.b32 %0, 1, 0, p;\n\t}" : "=r"(_d) : "r"(_m), "r"(_p) : "memory"); \
    if (!_d) { \
        asm volatile("{\n\t.reg .pred P1;\n\t" \
            "WL_%=:\n\t" \
            "mbarrier.try_wait.parity.acquire.cta.shared::cta.b64 P1, [%0], %1, 0x989680;\n\t" \
            "@P1 bra.uni WD_%=;\n\t" \
            "bra.uni WL_%=;\n\t" \
            "WD_%=:\n\t}" :: "r"(_m), "r"(_p) : "memory"); \
    } \
} while (0)
#endif  // GEMM_TC

template<int MODE>
__global__ __launch_bounds__(256)
void gemm_any(const float* __restrict__ A, const float* __restrict__ Bt,
              const float* __restrict__ bias, const float* __restrict__ res,
              float* __restrict__ C, int M, int N, int K)
{
    extern __shared__ __align__(1024) char gsm[];
    const int tid = threadIdx.x, wid = tid >> 5, lane = tid & 31;
    const int m0 = blockIdx.y * 128, n0 = blockIdx.x * 128;

#if GEMM_TC
    // ================= tcgen05 path =================
    const uint32_t sb = (uint32_t)__cvta_generic_to_shared(gsm);
    const uint32_t mb0 = sb + 16, mb1 = sb + 24;

    if (wid == 0) {
        asm volatile("tcgen05.alloc.cta_group::1.sync.aligned.shared::cta.b32 [%0], %1;"
                     :: "r"(sb), "r"(128u) : "memory");
        asm volatile("tcgen05.relinquish_alloc_permit.cta_group::1.sync.aligned;");
    }
    if (tid == 0) { MBAR_INIT(mb0, 1); MBAR_INIT(mb1, 1); }
    __syncthreads();
    uint32_t tb;
    asm volatile("ld.shared.b32 %0, [%1];" : "=r"(tb) : "r"(sb));

    const int KT = K >> 5;

    auto fill = [&](int slot, int ktile) {
        uint32_t s = sb + G_BASE + slot * G_STAGE;
        const float* Ap = A  + (size_t)m0 * K + ktile * 32;
        const float* Bp = Bt + (size_t)n0 * K + ktile * 32;
        #pragma unroll
        for (int i = 0; i < 4; i++) {
            int idx = tid + i * 256;          // 0..1023 chunks of 16B
            int r = idx >> 3, ch = (idx & 7) * 16;
            uint32_t byte = (uint32_t)(r * 128 + ch);
            uint32_t sw = byte ^ ((byte >> 3) & 0x70);
            cp16(s + sw,          Ap + (size_t)r * K + (ch >> 2));
            cp16(s + G_TILE + sw, Bp + (size_t)r * K + (ch >> 2));
        }
    };

    #pragma unroll
    for (int st = 0; st < GS - 1; st++) {
        fill(st, st);
        asm volatile("cp.async.commit_group;" ::: "memory");
    }

    // idesc: accum F32, atype=btype=TF32(2), N=128, M=128 (K-major both)
    const uint32_t idesc = (1u << 4) | (2u << 7) | (2u << 10)
                         | (16u << 17) | (8u << 24);

    int ph0 = 0, ph1 = 0;
    for (int kt = 0; kt < KT; kt++) {
        asm volatile("cp.async.wait_group %0;" :: "n"(GS - 2) : "memory");
        asm volatile("fence.proxy.async.shared::cta;" ::: "memory");
        __syncthreads();

        if (wid == 0 && elect_one()) {
            uint32_t s = sb + G_BASE + (kt % GS) * G_STAGE;
            uint64_t ad = make_desc(s);
            uint64_t bd = make_desc(s + G_TILE);
            #pragma unroll
            for (int ks = 0; ks < 4; ks++)
                tc_mma_tf32_ss(tb, ad + ks * 2, bd + ks * 2, idesc, (kt > 0) || (ks > 0));
            uint32_t mb = (kt & 1) ? mb1 : mb0;
            asm volatile(
                "tcgen05.commit.cta_group::1.mbarrier::arrive::one.shared::cluster.b64 [%0];"
                :: "r"(mb) : "memory");
        }

        if (kt >= 1) {
            if ((kt - 1) & 1) { MBAR_WAIT(mb1, ph1); ph1 ^= 1; }
            else              { MBAR_WAIT(mb0, ph0); ph0 ^= 1; }
        }
        if (kt + GS - 1 < KT) fill((kt + GS - 1) % GS, kt + GS - 1);
        asm volatile("cp.async.commit_group;" ::: "memory");
    }

    if ((KT - 1) & 1) { MBAR_WAIT(mb1, ph1); }
    else              { MBAR_WAIT(mb0, ph0); }
    asm volatile("tcgen05.fence::after_thread_sync;" ::: "memory");

    if (wid < 4) {
        const int row = m0 + wid * 32 + lane;
        #pragma unroll
        for (int c0 = 0; c0 < 128; c0 += 32) {
            float d[32];
            asm volatile(
                "tcgen05.ld.sync.aligned.32x32b.x32.b32 "
                "{%0,%1,%2,%3,%4,%5,%6,%7,%8,%9,%10,%11,%12,%13,%14,%15,"
                "%16,%17,%18,%19,%20,%21,%22,%23,%24,%25,%26,%27,%28,%29,%30,%31}, [%32];"
                : "=f"(d[0]),  "=f"(d[1]),  "=f"(d[2]),  "=f"(d[3]),
                  "=f"(d[4]),  "=f"(d[5]),  "=f"(d[6]),  "=f"(d[7]),
                  "=f"(d[8]),  "=f"(d[9]),  "=f"(d[10]), "=f"(d[11]),
                  "=f"(d[12]), "=f"(d[13]), "=f"(d[14]), "=f"(d[15]),
                  "=f"(d[16]), "=f"(d[17]), "=f"(d[18]), "=f"(d[19]),
                  "=f"(d[20]), "=f"(d[21]), "=f"(d[22]), "=f"(d[23]),
                  "=f"(d[24]), "=f"(d[25]), "=f"(d[26]), "=f"(d[27]),
                  "=f"(d[28]), "=f"(d[29]), "=f"(d[30]), "=f"(d[31])
                : "r"(tb + c0));
            asm volatile("tcgen05.wait::ld.sync.aligned;" ::: "memory");

            #pragma unroll
            for (int c = 0; c < 32; c += 4) {
                const float4 bv = *(const float4*)(bias + n0 + c0 + c);
                float4 v;
                v.x = d[c + 0] + bv.x; v.y = d[c + 1] + bv.y;
                v.z = d[c + 2] + bv.z; v.w = d[c + 3] + bv.w;
                if (MODE == 1) {
                    const float4 rv = *(const float4*)(res + (size_t)row * N + n0 + c0 + c);
                    v.x += rv.x; v.y += rv.y; v.z += rv.z; v.w += rv.w;
                }
                if (MODE == 2) {
                    v.x = gelu_exact(v.x); v.y = gelu_exact(v.y);
                    v.z = gelu_exact(v.z); v.w = gelu_exact(v.w);
                }
                if (MODE == 0 || MODE == 2) {
                    v.x = to_tf32(v.x); v.y = to_tf32(v.y);
                    v.z = to_tf32(v.z); v.w = to_tf32(v.w);
                }
                *(float4*)(C + (size_t)row * N + n0 + c0 + c) = v;
            }
        }
    }

    __syncthreads();
    if (tid == 0) {
        asm volatile("mbarrier.inval.shared.b64 [%0];" :: "r"(mb0) : "memory");
        asm volatile("mbarrier.inval.shared.b64 [%0];" :: "r"(mb1) : "memory");
    }
    __syncthreads();
    if (wid == 0)
        asm volatile("tcgen05.dealloc.cta_group::1.sync.aligned.b32 %0, %1;"
                     :: "r"(tb), "r"(128u));

#else
    // ================= mma.sync fallback (proven R3 structure) =================
    float* As = (float*)gsm;              // [2][16][132]
    float* Bs = As + 2 * 16 * 132;        // [2][16][132]
    #define AS(buf, k, m) As[((buf) * 16 + (k)) * 132 + (m)]
    #define BS(buf, k, n) Bs[((buf) * 16 + (k)) * 132 + (n)]

    const int w = wid;
    const int wm = w >> 2, wn = w & 3;
    const int gp = lane >> 2, tg = lane & 3;

    float c[4][4][4];
    #pragma unroll
    for (int i = 0; i < 4; i++)
        #pragma unroll
        for (int j = 0; j < 4; j++)
            #pragma unroll
            for (int r = 0; r < 4; r++) c[i][j][r] = 0.f;

    const int KT = K >> 4;
    float4 va[2], vb[2];

    #pragma unroll
    for (int i = 0; i < 2; i++) {
        int idx = tid + i * 256;
        int r = idx >> 2, c4 = (idx & 3) << 2;
        va[i] = *(const float4*)(A  + (size_t)(m0 + r) * K + c4);
        vb[i] = *(const float4*)(Bt + (size_t)(n0 + r) * K + c4);
    }
    #pragma unroll
    for (int i = 0; i < 2; i++) {
        int idx = tid + i * 256;
        int r = idx >> 2, c4 = (idx & 3) << 2;
        AS(0, c4 + 0, r) = to_tf32(va[i].x);
        AS(0, c4 + 1, r) = to_tf32(va[i].y);
        AS(0, c4 + 2, r) = to_tf32(va[i].z);
        AS(0, c4 + 3, r) = to_tf32(va[i].w);
        BS(0, c4 + 0, r) = to_tf32(vb[i].x);
        BS(0, c4 + 1, r) = to_tf32(vb[i].y);
        BS(0, c4 + 2, r) = to_tf32(vb[i].z);
        BS(0, c4 + 3, r) = to_tf32(vb[i].w);
    }
    __syncthreads();

    int cur = 0;
    for (int kt = 0; kt < KT; kt++) {
        if (kt + 1 < KT) {
            #pragma unroll
            for (int i = 0; i < 2; i++) {
                int idx = tid + i * 256;
                int r = idx >> 2, c4 = (idx & 3) << 2;
                va[i] = *(const float4*)(A  + (size_t)(m0 + r) * K + (kt + 1) * 16 + c4);
                vb[i] = *(const float4*)(Bt + (size_t)(n0 + r) * K + (kt + 1) * 16 + c4);
            }
        }
        #pragma unroll
        for (int ks = 0; ks < 2; ks++) {
            const int k = ks * 8;
            uint32_t a[4][4], b[4][2];
            #pragma unroll
            for (int mf = 0; mf < 4; mf++) {
                int r0 = wm * 64 + mf * 16;
                a[mf][0] = __float_as_uint(AS(cur, k + tg,     r0 + gp));
                a[mf][1] = __float_as_uint(AS(cur, k + tg,     r0 + gp + 8));
                a[mf][2] = __float_as_uint(AS(cur, k + tg + 4, r0 + gp));
                a[mf][3] = __float_as_uint(AS(cur, k + tg + 4, r0 + gp + 8));
            }
            #pragma unroll
            for (int nf = 0; nf < 4; nf++) {
                int c0 = wn * 32 + nf * 8;
                b[nf][0] = __float_as_uint(BS(cur, k + tg,     c0 + gp));
                b[nf][1] = __float_as_uint(BS(cur, k + tg + 4, c0 + gp));
            }
            #pragma unroll
            for (int mf = 0; mf < 4; mf++)
                #pragma unroll
                for (int nf = 0; nf < 4; nf++)
                    mma_tf32(c[mf][nf], a[mf][0], a[mf][1], a[mf][2], a[mf][3],
                             b[nf][0], b[nf][1]);
        }
        if (kt + 1 < KT) {
            int nxt = cur ^ 1;
            #pragma unroll
            for (int i = 0; i < 2; i++) {
                int idx = tid + i * 256;
                int r = idx >> 2, c4 = (idx & 3) << 2;
                AS(nxt, c4 + 0, r) = to_tf32(va[i].x);
                AS(nxt, c4 + 1, r) = to_tf32(va[i].y);
                AS(nxt, c4 + 2, r) = to_tf32(va[i].z);
                AS(nxt, c4 + 3, r) = to_tf32(va[i].w);
                BS(nxt, c4 + 0, r) = to_tf32(vb[i].x);
                BS(nxt, c4 + 1, r) = to_tf32(vb[i].y);
                BS(nxt, c4 + 2, r) = to_tf32(vb[i].z);
                BS(nxt, c4 + 3, r) = to_tf32(vb[i].w);
            }
            __syncthreads();
            cur = nxt;
        }
    }

    #pragma unroll
    for (int mf = 0; mf < 4; mf++) {
        #pragma unroll
        for (int nf = 0; nf < 4; nf++) {
            int col = n0 + wn * 32 + nf * 8 + 2 * tg;
            float bi0 = bias[col], bi1 = bias[col + 1];
            #pragma unroll
            for (int hh = 0; hh < 2; hh++) {
                int row = m0 + wm * 64 + mf * 16 + gp + hh * 8;
                float v0 = c[mf][nf][hh * 2 + 0] + bi0;
                float v1 = c[mf][nf][hh * 2 + 1] + bi1;
                if (MODE == 1) {
                    const float2 rv = *(const float2*)(res + (size_t)row * N + col);
                    v0 += rv.x; v1 += rv.y;
                }
                if (MODE == 2) { v0 = gelu_exact(v0); v1 = gelu_exact(v1); }
                if (MODE == 0 || MODE == 2) { v0 = to_tf32(v0); v1 = to_tf32(v1); }
                float2 o; o.x = v0; o.y = v1;
                *(float2*)(C + (size_t)row * N + col) = o;
            }
        }
    }
    #undef AS
    #undef BS
#endif
}

// ---------------- causal flash attention (unchanged; writes tf32-rounded y) ----------------
#define AT_STRIDE 76
#define AT_BUF    (64 * AT_STRIDE)
#define ATTN_SMEM ((4 * AT_BUF) * 4 + 2 * 64 * 4)

__global__ __launch_bounds__(256) void attn_kernel(
    const float* __restrict__ qkv, const int* __restrict__ amask,
    float* __restrict__ y)
{
    extern __shared__ float sm[];
    float* kb = sm;
    float* vb = sm + 2 * AT_BUF;
    int*   mk = (int*)(sm + 4 * AT_BUF);

    const int tid = threadIdx.x, lane = tid & 31, w = tid >> 5;
    const int gp = lane >> 2, tg = lane & 3;
    const int h = blockIdx.y;
    const int q0 = (gridDim.x - 1 - blockIdx.x) * 128;
    const int qw = q0 + w * 16;

    #pragma unroll
    for (int i = 0; i < 8; i++) {
        int idx = tid + i * 256;
        int r = idx >> 4, c4 = (idx & 15) << 2;
        const float4 v = *(const float4*)(qkv + (size_t)(q0 + r) * (3 * DM) + h * HDIM + c4);
        float* dst = (r < 64 ? (kb + AT_BUF) : (vb + AT_BUF)) + (r & 63) * AT_STRIDE + c4;
        *(float4*)dst = v;
    }

    {
        int r = tid >> 2, cg = (tid & 3) << 4;
        const float* gk = qkv + (size_t)r * (3 * DM) + DM + h * HDIM + cg;
        uint32_t dk = (uint32_t)__cvta_generic_to_shared(kb + r * AT_STRIDE + cg);
        uint32_t dv = (uint32_t)__cvta_generic_to_shared(vb + r * AT_STRIDE + cg);
        #pragma unroll
        for (int i = 0; i < 4; i++) {
            cp16(dk + i * 16, gk + i * 4);
            cp16(dv + i * 16, gk + DM + i * 4);
        }
        if (tid < 16) {
            uint32_t dm = (uint32_t)__cvta_generic_to_shared(mk + tid * 4);
            cp16(dm, amask + tid * 4);
        }
    }
    asm volatile("cp.async.commit_group;\n" ::: "memory");
    __syncthreads();

    uint32_t qa[8][4];
    {
        const float* st = (w < 4 ? (kb + AT_BUF) : (vb + AT_BUF));
        int r0 = (w * 16) & 63;
        #pragma unroll
        for (int ks = 0; ks < 8; ks++) {
            qa[ks][0] = to_tf32_u(st[(r0 + gp    ) * AT_STRIDE + ks * 8 + tg    ]);
            qa[ks][1] = to_tf32_u(st[(r0 + gp + 8) * AT_STRIDE + ks * 8 + tg    ]);
            qa[ks][2] = to_tf32_u(st[(r0 + gp    ) * AT_STRIDE + ks * 8 + tg + 4]);
            qa[ks][3] = to_tf32_u(st[(r0 + gp + 8) * AT_STRIDE + ks * 8 + tg + 4]);
        }
    }

    float m0 = -INFINITY, m1 = -INFINITY, l0 = 0.f, l1 = 0.f;
    float o[8][4];
    #pragma unroll
    for (int nf = 0; nf < 8; nf++)
        #pragma unroll
        for (int r = 0; r < 4; r++) o[nf][r] = 0.f;

    const int ktmax = (q0 + 127) >> 6;
    const int row0 = qw + gp, row1 = qw + gp + 8;
    int cur = 0;

    for (int kt = 0; kt <= ktmax; kt++) {
        asm volatile("cp.async.wait_group 0;\n" ::: "memory");
        __syncthreads();

        if (kt < ktmax) {
            int nb = cur ^ 1;
            int r = tid >> 2, cg = (tid & 3) << 4;
            const float* gk = qkv + (size_t)((kt + 1) * 64 + r) * (3 * DM) + DM + h * HDIM + cg;
            uint32_t dk = (uint32_t)__cvta_generic_to_shared(kb + nb * AT_BUF + r * AT_STRIDE + cg);
            uint32_t dv = (uint32_t)__cvta_generic_to_shared(vb + nb * AT_BUF + r * AT_STRIDE + cg);
            #pragma unroll
            for (int i = 0; i < 4; i++) {
                cp16(dk + i * 16, gk + i * 4);
                cp16(dv + i * 16, gk + DM + i * 4);
            }
            if (tid < 16) {
                uint32_t dm = (uint32_t)__cvta_generic_to_shared(mk + nb * 64 + tid * 4);
                cp16(dm, amask + (kt + 1) * 64 + tid * 4);
            }
            asm volatile("cp.async.commit_group;\n" ::: "memory");
        }

        const float* K = kb + cur * AT_BUF;
        const float* V = vb + cur * AT_BUF;
        const int*   M = mk + cur * 64;

        float sc[8][4];
        #pragma unroll
        for (int nf = 0; nf < 8; nf++)
            #pragma unroll
            for (int r = 0; r < 4; r++) sc[nf][r] = 0.f;

        #pragma unroll
        for (int ks = 0; ks < 8; ks++) {
            #pragma unroll
            for (int nf = 0; nf < 8; nf++) {
                uint32_t b0 = __float_as_uint(K[(nf * 8 + gp) * AT_STRIDE + ks * 8 + tg    ]);
                uint32_t b1 = __float_as_uint(K[(nf * 8 + gp) * AT_STRIDE + ks * 8 + tg + 4]);
                mma_tf32(sc[nf], qa[ks][0], qa[ks][1], qa[ks][2], qa[ks][3], b0, b1);
            }
        }

        float tm0 = -INFINITY, tm1 = -INFINITY;
        #pragma unroll
        for (int nf = 0; nf < 8; nf++) {
            int cl = nf * 8 + 2 * tg;
            int c  = kt * 64 + cl;
            bool mk0 = M[cl] != 0, mk1 = M[cl + 1] != 0;
            float s0 = sc[nf][0] * 0.125f, s1 = sc[nf][1] * 0.125f;
            float s2 = sc[nf][2] * 0.125f, s3 = sc[nf][3] * 0.125f;
            s0 = (c     <= row0 && mk0) ? s0 : -INFINITY;
            s1 = (c + 1 <= row0 && mk1) ? s1 : -INFINITY;
            s2 = (c     <= row1 && mk0) ? s2 : -INFINITY;
            s3 = (c + 1 <= row1 && mk1) ? s3 : -INFINITY;
            sc[nf][0] = s0; sc[nf][1] = s1; sc[nf][2] = s2; sc[nf][3] = s3;
            tm0 = fmaxf(tm0, fmaxf(s0, s1));
            tm1 = fmaxf(tm1, fmaxf(s2, s3));
        }
        tm0 = fmaxf(tm0, __shfl_xor_sync(0xffffffffu, tm0, 1));
        tm0 = fmaxf(tm0, __shfl_xor_sync(0xffffffffu, tm0, 2));
        tm1 = fmaxf(tm1, __shfl_xor_sync(0xffffffffu, tm1, 1));
        tm1 = fmaxf(tm1, __shfl_xor_sync(0xffffffffu, tm1, 2));

        float nm0 = fmaxf(m0, tm0), nm1 = fmaxf(m1, tm1);
        float ne0 = fmaxf(nm0, -1e30f), ne1 = fmaxf(nm1, -1e30f);
        float al0 = __expf(m0 - ne0), al1 = __expf(m1 - ne1);
        m0 = nm0; m1 = nm1;

        float ps0 = 0.f, ps1 = 0.f;
        #pragma unroll
        for (int nf = 0; nf < 8; nf++) {
            float p0 = __expf(sc[nf][0] - ne0);
            float p1 = __expf(sc[nf][1] - ne0);
            float p2 = __expf(sc[nf][2] - ne1);
            float p3 = __expf(sc[nf][3] - ne1);
            sc[nf][0] = p0; sc[nf][1] = p1; sc[nf][2] = p2; sc[nf][3] = p3;
            ps0 += p0 + p1; ps1 += p2 + p3;
        }
        ps0 += __shfl_xor_sync(0xffffffffu, ps0, 1);
        ps0 += __shfl_xor_sync(0xffffffffu, ps0, 2);
        ps1 += __shfl_xor_sync(0xffffffffu, ps1, 1);
        ps1 += __shfl_xor_sync(0xffffffffu, ps1, 2);
        l0 = l0 * al0 + ps0;
        l1 = l1 * al1 + ps1;

        #pragma unroll
        for (int nf = 0; nf < 8; nf++) {
            o[nf][0] *= al0; o[nf][1] *= al0;
            o[nf][2] *= al1; o[nf][3] *= al1;
        }

        const int src0 = (lane & ~3) | (tg >> 1);
        const int src1 = src0 + 2;
        const bool odd = (tg & 1) != 0;
        #pragma unroll
        for (int ks = 0; ks < 8; ks++) {
            float e00 = __shfl_sync(0xffffffffu, sc[ks][0], src0);
            float e01 = __shfl_sync(0xffffffffu, sc[ks][1], src0);
            float e10 = __shfl_sync(0xffffffffu, sc[ks][2], src0);
            float e11 = __shfl_sync(0xffffffffu, sc[ks][3], src0);
            float f00 = __shfl_sync(0xffffffffu, sc[ks][0], src1);
            float f01 = __shfl_sync(0xffffffffu, sc[ks][1], src1);
            float f10 = __shfl_sync(0xffffffffu, sc[ks][2], src1);
            float f11 = __shfl_sync(0xffffffffu, sc[ks][3], src1);
            uint32_t pa0 = to_tf32_u(odd ? e01 : e00);
            uint32_t pa1 = to_tf32_u(odd ? e11 : e10);
            uint32_t pa2 = to_tf32_u(odd ? f01 : f00);
            uint32_t pa3 = to_tf32_u(odd ? f11 : f10);
            #pragma unroll
            for (int nf = 0; nf < 8; nf++) {
                uint32_t b0 = __float_as_uint(V[(ks * 8 + tg    ) * AT_STRIDE + nf * 8 + gp]);
                uint32_t b1 = __float_as_uint(V[(ks * 8 + tg + 4) * AT_STRIDE + nf * 8 + gp]);
                mma_tf32(o[nf], pa0, pa1, pa2, pa3, b0, b1);
            }
        }
        cur ^= 1;
    }

    float il0 = 1.0f / fmaxf(l0, 1e-30f);
    float il1 = 1.0f / fmaxf(l1, 1e-30f);
    #pragma unroll
    for (int nf = 0; nf < 8; nf++) {
        int col = h * HDIM + nf * 8 + 2 * tg;
        float2 v0; v0.x = to_tf32(o[nf][0] * il0); v0.y = to_tf32(o[nf][1] * il0);
        *(float2*)(y + (size_t)row0 * DM + col) = v0;
        float2 v1; v1.x = to_tf32(o[nf][2] * il1); v1.y = to_tf32(o[nf][3] * il1);
        *(float2*)(y + (size_t)row1 * DM + col) = v1;
    }
}

// ---------------- launcher ----------------
extern "C" void kernel_launch(void* const* d_in, const int* in_sizes, int n_in,
                              void* d_out, int out_size)
{
    const float* x     = (const float*)d_in[0];
    const int*   amask = (const int*)  d_in[1];
    const float* ln1g  = (const float*)d_in[2];
    const float* ln1b  = (const float*)d_in[3];
    const float* Wqkv  = (const float*)d_in[4];
    const float* bqkv  = (const float*)d_in[5];
    const float* Wo    = (const float*)d_in[6];
    const float* bo    = (const float*)d_in[7];
    const float* ln2g  = (const float*)d_in[8];
    const float* ln2b  = (const float*)d_in[9];
    const float* W1    = (const float*)d_in[10];
    const float* b1    = (const float*)d_in[11];
    const float* W2    = (const float*)d_in[12];
    const float* b2    = (const float*)d_in[13];
    float* out = (float*)d_out;

    void *p_ln, *p_qkv, *p_y, *p_x2, *p_ff;
    void *p_wqkv, *p_wo, *p_w1, *p_w2;
    cudaGetSymbolAddress(&p_ln,   g_ln);
    cudaGetSymbolAddress(&p_qkv,  g_qkv);
    cudaGetSymbolAddress(&p_y,    g_y);
    cudaGetSymbolAddress(&p_x2,   g_x2);
    cudaGetSymbolAddress(&p_ff,   g_ff);
    cudaGetSymbolAddress(&p_wqkv, g_wt_qkv);
    cudaGetSymbolAddress(&p_wo,   g_wt_o);
    cudaGetSymbolAddress(&p_w1,   g_wt_1);
    cudaGetSymbolAddress(&p_w2,   g_wt_2);

    cudaFuncSetAttribute(attn_kernel,
        cudaFuncAttributeMaxDynamicSharedMemorySize, ATTN_SMEM);
    cudaFuncSetAttribute(gemm_any<0>,
        cudaFuncAttributeMaxDynamicSharedMemorySize, G_SMEM);
    cudaFuncSetAttribute(gemm_any<1>,
        cudaFuncAttributeMaxDynamicSharedMemorySize, G_SMEM);
    cudaFuncSetAttribute(gemm_any<2>,
        cudaFuncAttributeMaxDynamicSharedMemorySize, G_SMEM);

    // 0. weight transposes (tf32-rounded, [N,K])
    transpose_kernel<<<dim3(3 * DM / 32, DM / 32), 256>>>(Wqkv, (float*)p_wqkv, DM, 3 * DM);
    transpose_kernel<<<dim3(DM / 32, DM / 32),     256>>>(Wo,   (float*)p_wo,   DM, DM);
    transpose_kernel<<<dim3(DFF / 32, DM / 32),    256>>>(W1,   (float*)p_w1,   DM, DFF);
    transpose_kernel<<<dim3(DM / 32, DFF / 32),    256>>>(W2,   (float*)p_w2,   DFF, DM);

    // 1. LN1
    ln_kernel<<<T_SEQ, 256>>>(x, ln1g, ln1b, (float*)p_ln);
    // 2. QKV
    gemm_any<0><<<dim3(24, 32), 256, G_SMEM>>>((float*)p_ln, (float*)p_wqkv, bqkv, nullptr,
                                               (float*)p_qkv, T_SEQ, 3 * DM, DM);
    // 3. attention
    attn_kernel<<<dim3(32, 16), 256, ATTN_SMEM>>>((float*)p_qkv, amask, (float*)p_y);
    // 4. x2 = x + y @ W_o + b_o
    gemm_any<1><<<dim3(8, 32), 256, G_SMEM>>>((float*)p_y, (float*)p_wo, bo, x,
                                              (float*)p_x2, T_SEQ, DM, DM);
    // 5. LN2
    ln_kernel<<<T_SEQ, 256>>>((float*)p_x2, ln2g, ln2b, (float*)p_ln);
    // 6. ff = gelu(h2 @ W1 + b1)
    gemm_any<2><<<dim3(32, 32), 256, G_SMEM>>>((float*)p_ln, (float*)p_w1, b1, nullptr,
                                               (float*)p_ff, T_SEQ, DFF, DM);
    // 7. out = x2 + ff @ W2 + b2
    gemm_any<1><<<dim3(8, 32), 256, G_SMEM>>>((float*)p_ff, (float*)p_w2, b2, (float*)p_x2,
                                              out, T_SEQ, DM, DFF);
}

// round 6
// speedup vs baseline: 1.8604x; 1.0329x over previous
#include <cuda_runtime.h>
#include <cstdint>
#include <math.h>

#define T_SEQ   4096
#define DM      1024
#define DFF     4096
#define NHEADS  16
#define HDIM    64
#define LN_EPS  1e-5f

// ---- arch-specific feature gate: tcgen05 only exists on sm_10xa/f targets ----
#if defined(__CUDA_ARCH__)
#  if defined(__CUDA_ARCH_FEAT_SM103_ALL) || defined(__CUDA_ARCH_FEAT_SM100_ALL) || defined(__CUDA_ARCH_FEAT_SM101_ALL)
#    define GEMM_TC 1
#  elif defined(__CUDA_ARCH_SPECIFIC__)
#    define GEMM_TC ((__CUDA_ARCH_SPECIFIC__ >= 1000) ? 1 : 0)
#  elif defined(__CUDA_ARCH_FAMILY_SPECIFIC__)
#    define GEMM_TC ((__CUDA_ARCH_FAMILY_SPECIFIC__ >= 1000) ? 1 : 0)
#  else
#    define GEMM_TC 0
#  endif
#else
#  define GEMM_TC 0
#endif

// ---------------- scratch (static device globals; no allocation) ----------------
static __device__ float g_ln [T_SEQ * DM];
static __device__ float g_qkv[T_SEQ * 3 * DM];
static __device__ float g_y  [T_SEQ * DM];
static __device__ float g_x2 [T_SEQ * DM];
static __device__ float g_ff [T_SEQ * DFF];
// transposed (tf32-rounded) weights, [N, K] K-major
static __device__ float g_wt_qkv[3 * DM * DM];
static __device__ float g_wt_o  [DM * DM];
static __device__ float g_wt_1  [DFF * DM];
static __device__ float g_wt_2  [DM * DFF];

// ---------------- helpers ----------------
__device__ __forceinline__ float to_tf32(float x) {
    uint32_t u;
    asm("cvt.rna.tf32.f32 %0, %1;" : "=r"(u) : "f"(x));
    return __uint_as_float(u);
}
__device__ __forceinline__ uint32_t to_tf32_u(float x) {
    uint32_t u;
    asm("cvt.rna.tf32.f32 %0, %1;" : "=r"(u) : "f"(x));
    return u;
}

__device__ __forceinline__ void mma_tf32(float* c,
    uint32_t a0, uint32_t a1, uint32_t a2, uint32_t a3,
    uint32_t b0, uint32_t b1)
{
    asm volatile(
        "mma.sync.aligned.m16n8k8.row.col.f32.tf32.tf32.f32 "
        "{%0,%1,%2,%3}, {%4,%5,%6,%7}, {%8,%9}, {%0,%1,%2,%3};\n"
        : "+f"(c[0]), "+f"(c[1]), "+f"(c[2]), "+f"(c[3])
        : "r"(a0), "r"(a1), "r"(a2), "r"(a3), "r"(b0), "r"(b1));
}

__device__ __forceinline__ void cp16(uint32_t dst, const void* src) {
    asm volatile("cp.async.ca.shared.global [%0], [%1], 16;\n"
                 :: "r"(dst), "l"(src));
}

__device__ __forceinline__ float gelu_exact(float v) {
    return 0.5f * v * (1.0f + erff(v * 0.70710678118654752440f));
}

// ---------------- weight transpose + tf32 round:  out[n][k] = rn(in[k][n]) ----------------
__global__ __launch_bounds__(256) void transpose_kernel(
    const float* __restrict__ in, float* __restrict__ out, int R, int C)
{
    __shared__ float t[32][33];
    int bx = blockIdx.x * 32, by = blockIdx.y * 32;
    int x = threadIdx.x & 31, y = threadIdx.x >> 5;
    #pragma unroll
    for (int i = 0; i < 32; i += 8)
        t[y + i][x] = in[(size_t)(by + y + i) * C + bx + x];
    __syncthreads();
    #pragma unroll
    for (int i = 0; i < 32; i += 8)
        out[(size_t)(bx + y + i) * R + by + x] = to_tf32(t[x][y + i]);
}

// ---------------- LayerNorm (writes tf32-rounded output) ----------------
__global__ __launch_bounds__(256) void ln_kernel(
    const float* __restrict__ x, const float* __restrict__ g,
    const float* __restrict__ b, float* __restrict__ out)
{
    int row = blockIdx.x;
    int tid = threadIdx.x;
    const float4 v = ((const float4*)(x + (size_t)row * DM))[tid];
    float s  = v.x + v.y + v.z + v.w;
    float sq = v.x * v.x + v.y * v.y + v.z * v.z + v.w * v.w;
    #pragma unroll
    for (int o = 16; o; o >>= 1) {
        s  += __shfl_xor_sync(0xffffffffu, s,  o);
        sq += __shfl_xor_sync(0xffffffffu, sq, o);
    }
    __shared__ float ss[8], ssq[8];
    __shared__ float mean_s, inv_s;
    int w = tid >> 5, l = tid & 31;
    if (l == 0) { ss[w] = s; ssq[w] = sq; }
    __syncthreads();
    if (tid == 0) {
        float st = 0.f, sqt = 0.f;
        #pragma unroll
        for (int i = 0; i < 8; i++) { st += ss[i]; sqt += ssq[i]; }
        float mean = st * (1.0f / DM);
        float var  = sqt * (1.0f / DM) - mean * mean;
        mean_s = mean;
        inv_s  = rsqrtf(var + LN_EPS);
    }
    __syncthreads();
    float mean = mean_s, inv = inv_s;
    const float4 gv = ((const float4*)g)[tid];
    const float4 bv = ((const float4*)b)[tid];
    float4 o;
    o.x = to_tf32((v.x - mean) * inv * gv.x + bv.x);
    o.y = to_tf32((v.y - mean) * inv * gv.y + bv.y);
    o.z = to_tf32((v.z - mean) * inv * gv.z + bv.z);
    o.w = to_tf32((v.w - mean) * inv * gv.w + bv.w);
    ((float4*)(out + (size_t)row * DM))[tid] = o;
}

// ---------------- unified GEMM: C[M,N] = A[M,K] @ Bt[N,K]^T + epilogue --------
// Tile 128x256, 256 threads. grid = (N/256, M/128).
// TC path (sm_10xa/f): tcgen05 SS tf32, BK=32, 3-stage cp.async ring, TMEM D=256 cols.
// Fallback: proven mma.sync 128x128 body, run twice (two N-halves).
// MODE 0: +bias, round tf32   MODE 1: +bias+res (fp32)   MODE 2: gelu(+bias), round
#define GS       3
#define G_TILE_A 16384
#define G_TILE_B 32768
#define G_STAGE  (G_TILE_A + G_TILE_B)      // 49152
#define G_BASE   1024
#define G_SMEM   (G_BASE + GS * G_STAGE)    // 148480

#if GEMM_TC
__device__ __forceinline__ bool elect_one() {
    uint32_t pred;
    asm volatile(
        "{\n\t.reg .pred p;\n\t"
        "elect.sync _|p, 0xFFFFFFFF;\n\t"
        "selp.b32 %0, 1, 0, p;\n\t}"
        : "=r"(pred));
    return pred != 0;
}
__device__ __forceinline__ uint64_t make_desc(uint32_t addr) {
    const uint64_t base = (2ULL << 61) | (1ULL << 46) | (64ULL << 32) | (1ULL << 16);
    return base | ((uint64_t)(addr >> 4) & 0x3FFF);
}
__device__ __forceinline__ void tc_mma_tf32_ss(uint32_t d, uint64_t ad, uint64_t bd,
                                               uint32_t idesc, bool acc)
{
    uint32_t en = acc ? 1u : 0u;
    asm volatile(
        "{\n\t.reg .pred p;\n\t"
        "setp.ne.u32 p, %4, 0;\n\t"
        "tcgen05.mma.cta_group::1.kind::tf32 [%0], %1, %2, %3, {%5, %5, %5, %5}, p;\n\t}"
        :: "r"(d), "l"(ad), "l"(bd), "r"(idesc), "r"(en), "r"(0u)
        : "memory");
}
#define MBAR_INIT(a, c) \
    asm volatile("mbarrier.init.shared.b64 [%0], %1;" :: "r"(a), "r"(c) : "memory")
#define MBAR_WAIT(a, par) do { \
    uint32_t _m = (a), _p = (par), _d; \
    asm volatile("{\n\t.reg .pred p;\n\t" \
        "mbarrier.try_wait.parity.acquire.cta.shared::cta.b64 p, [%1], %2;\n\t" \
        "selp.b32 %0, 1, 0, p;\n\t}" : "=r"(_d) : "r"(_m), "r"(_p) : "memory"); \
    if (!_d) { \
        asm volatile("{\n\t.reg .pred P1;\n\t" \
            "WL_%=:\n\t" \
            "mbarrier.try_wait.parity.acquire.cta.shared::cta.b64 P1, [%0], %1, 0x989680;\n\t" \
            "@P1 bra.uni WD_%=;\n\t" \
            "bra.uni WL_%=;\n\t" \
            "WD_%=:\n\t}" :: "r"(_m), "r"(_p) : "memory"); \
    } \
} while (0)
#endif  // GEMM_TC

template<int MODE>
__global__ __launch_bounds__(256)
void gemm_any(const float* __restrict__ A, const float* __restrict__ Bt,
              const float* __restrict__ bias, const float* __restrict__ res,
              float* __restrict__ C, int M, int N, int K)
{
    extern __shared__ __align__(1024) char gsm[];
    const int tid = threadIdx.x, wid = tid >> 5, lane = tid & 31;
    const int m0 = blockIdx.y * 128;

#if GEMM_TC
    // ================= tcgen05 path (128x256 tile) =================
    const int n0 = blockIdx.x * 256;
    const uint32_t sb = (uint32_t)__cvta_generic_to_shared(gsm);
    const uint32_t mb0 = sb + 16, mb1 = sb + 24;

    if (wid == 0) {
        asm volatile("tcgen05.alloc.cta_group::1.sync.aligned.shared::cta.b32 [%0], %1;"
                     :: "r"(sb), "r"(256u) : "memory");
        asm volatile("tcgen05.relinquish_alloc_permit.cta_group::1.sync.aligned;");
    }
    if (tid == 0) { MBAR_INIT(mb0, 1); MBAR_INIT(mb1, 1); }
    __syncthreads();
    uint32_t tb;
    asm volatile("ld.shared.b32 %0, [%1];" : "=r"(tb) : "r"(sb));

    const int KT = K >> 5;

    auto fill = [&](int slot, int ktile) {
        uint32_t s = sb + G_BASE + slot * G_STAGE;
        const float* Ap = A  + (size_t)m0 * K + ktile * 32;
        const float* Bp = Bt + (size_t)n0 * K + ktile * 32;
        // A: 128 rows x 128B
        #pragma unroll
        for (int i = 0; i < 4; i++) {
            int idx = tid + i * 256;
            int r = idx >> 3, ch = (idx & 7) * 16;
            uint32_t byte = (uint32_t)(r * 128 + ch);
            uint32_t sw = byte ^ ((byte >> 3) & 0x70);
            cp16(s + sw, Ap + (size_t)r * K + (ch >> 2));
        }
        // B: 256 rows x 128B
        #pragma unroll
        for (int i = 0; i < 8; i++) {
            int idx = tid + i * 256;
            int r = idx >> 3, ch = (idx & 7) * 16;
            uint32_t byte = (uint32_t)(r * 128 + ch);
            uint32_t sw = byte ^ ((byte >> 3) & 0x70);
            cp16(s + G_TILE_A + sw, Bp + (size_t)r * K + (ch >> 2));
        }
    };

    #pragma unroll
    for (int st = 0; st < GS - 1; st++) {
        fill(st, st);
        asm volatile("cp.async.commit_group;" ::: "memory");
    }

    // idesc: accum F32, atype=btype=TF32(2), N=256, M=128 (K-major both)
    const uint32_t idesc = (1u << 4) | (2u << 7) | (2u << 10)
                         | (32u << 17) | (8u << 24);

    int ph0 = 0, ph1 = 0;
    for (int kt = 0; kt < KT; kt++) {
        asm volatile("cp.async.wait_group %0;" :: "n"(GS - 2) : "memory");
        asm volatile("fence.proxy.async.shared::cta;" ::: "memory");
        __syncthreads();

        if (wid == 0 && elect_one()) {
            uint32_t s = sb + G_BASE + (kt % GS) * G_STAGE;
            uint64_t ad = make_desc(s);
            uint64_t bd = make_desc(s + G_TILE_A);
            #pragma unroll
            for (int ks = 0; ks < 4; ks++)
                tc_mma_tf32_ss(tb, ad + ks * 2, bd + ks * 2, idesc, (kt > 0) || (ks > 0));
            uint32_t mb = (kt & 1) ? mb1 : mb0;
            asm volatile(
                "tcgen05.commit.cta_group::1.mbarrier::arrive::one.shared::cluster.b64 [%0];"
                :: "r"(mb) : "memory");
        }

        if (kt >= 1) {
            if ((kt - 1) & 1) { MBAR_WAIT(mb1, ph1); ph1 ^= 1; }
            else              { MBAR_WAIT(mb0, ph0); ph0 ^= 1; }
        }
        if (kt + GS - 1 < KT) fill((kt + GS - 1) % GS, kt + GS - 1);
        asm volatile("cp.async.commit_group;" ::: "memory");
    }

    if ((KT - 1) & 1) { MBAR_WAIT(mb1, ph1); }
    else              { MBAR_WAIT(mb0, ph0); }
    asm volatile("tcgen05.fence::after_thread_sync;" ::: "memory");

    if (wid < 4) {
        const int row = m0 + wid * 32 + lane;
        #pragma unroll
        for (int c0 = 0; c0 < 256; c0 += 32) {
            float d[32];
            asm volatile(
                "tcgen05.ld.sync.aligned.32x32b.x32.b32 "
                "{%0,%1,%2,%3,%4,%5,%6,%7,%8,%9,%10,%11,%12,%13,%14,%15,"
                "%16,%17,%18,%19,%20,%21,%22,%23,%24,%25,%26,%27,%28,%29,%30,%31}, [%32];"
                : "=f"(d[0]),  "=f"(d[1]),  "=f"(d[2]),  "=f"(d[3]),
                  "=f"(d[4]),  "=f"(d[5]),  "=f"(d[6]),  "=f"(d[7]),
                  "=f"(d[8]),  "=f"(d[9]),  "=f"(d[10]), "=f"(d[11]),
                  "=f"(d[12]), "=f"(d[13]), "=f"(d[14]), "=f"(d[15]),
                  "=f"(d[16]), "=f"(d[17]), "=f"(d[18]), "=f"(d[19]),
                  "=f"(d[20]), "=f"(d[21]), "=f"(d[22]), "=f"(d[23]),
                  "=f"(d[24]), "=f"(d[25]), "=f"(d[26]), "=f"(d[27]),
                  "=f"(d[28]), "=f"(d[29]), "=f"(d[30]), "=f"(d[31])
                : "r"(tb + c0));
            asm volatile("tcgen05.wait::ld.sync.aligned;" ::: "memory");

            #pragma unroll
            for (int c = 0; c < 32; c += 4) {
                const float4 bv = *(const float4*)(bias + n0 + c0 + c);
                float4 v;
                v.x = d[c + 0] + bv.x; v.y = d[c + 1] + bv.y;
                v.z = d[c + 2] + bv.z; v.w = d[c + 3] + bv.w;
                if (MODE == 1) {
                    const float4 rv = *(const float4*)(res + (size_t)row * N + n0 + c0 + c);
                    v.x += rv.x; v.y += rv.y; v.z += rv.z; v.w += rv.w;
                }
                if (MODE == 2) {
                    v.x = gelu_exact(v.x); v.y = gelu_exact(v.y);
                    v.z = gelu_exact(v.z); v.w = gelu_exact(v.w);
                }
                if (MODE == 0 || MODE == 2) {
                    v.x = to_tf32(v.x); v.y = to_tf32(v.y);
                    v.z = to_tf32(v.z); v.w = to_tf32(v.w);
                }
                *(float4*)(C + (size_t)row * N + n0 + c0 + c) = v;
            }
        }
    }

    __syncthreads();
    if (tid == 0) {
        asm volatile("mbarrier.inval.shared.b64 [%0];" :: "r"(mb0) : "memory");
        asm volatile("mbarrier.inval.shared.b64 [%0];" :: "r"(mb1) : "memory");
    }
    __syncthreads();
    if (wid == 0)
        asm volatile("tcgen05.dealloc.cta_group::1.sync.aligned.b32 %0, %1;"
                     :: "r"(tb), "r"(256u));

#else
    // ================= mma.sync fallback: two 128x128 halves =================
    float* As = (float*)gsm;              // [2][16][132]
    float* Bs = As + 2 * 16 * 132;        // [2][16][132]
    #define AS(buf, k, m) As[((buf) * 16 + (k)) * 132 + (m)]
    #define BS(buf, k, n) Bs[((buf) * 16 + (k)) * 132 + (n)]

    const int w = wid;
    const int wm = w >> 2, wn = w & 3;
    const int gp = lane >> 2, tg = lane & 3;

    for (int half = 0; half < 2; half++) {
        const int n0 = blockIdx.x * 256 + half * 128;

        float c[4][4][4];
        #pragma unroll
        for (int i = 0; i < 4; i++)
            #pragma unroll
            for (int j = 0; j < 4; j++)
                #pragma unroll
                for (int r = 0; r < 4; r++) c[i][j][r] = 0.f;

        const int KT = K >> 4;
        float4 va[2], vb[2];

        __syncthreads();
        #pragma unroll
        for (int i = 0; i < 2; i++) {
            int idx = tid + i * 256;
            int r = idx >> 2, c4 = (idx & 3) << 2;
            va[i] = *(const float4*)(A  + (size_t)(m0 + r) * K + c4);
            vb[i] = *(const float4*)(Bt + (size_t)(n0 + r) * K + c4);
        }
        #pragma unroll
        for (int i = 0; i < 2; i++) {
            int idx = tid + i * 256;
            int r = idx >> 2, c4 = (idx & 3) << 2;
            AS(0, c4 + 0, r) = to_tf32(va[i].x);
            AS(0, c4 + 1, r) = to_tf32(va[i].y);
            AS(0, c4 + 2, r) = to_tf32(va[i].z);
            AS(0, c4 + 3, r) = to_tf32(va[i].w);
            BS(0, c4 + 0, r) = to_tf32(vb[i].x);
            BS(0, c4 + 1, r) = to_tf32(vb[i].y);
            BS(0, c4 + 2, r) = to_tf32(vb[i].z);
            BS(0, c4 + 3, r) = to_tf32(vb[i].w);
        }
        __syncthreads();

        int cur = 0;
        for (int kt = 0; kt < KT; kt++) {
            if (kt + 1 < KT) {
                #pragma unroll
                for (int i = 0; i < 2; i++) {
                    int idx = tid + i * 256;
                    int r = idx >> 2, c4 = (idx & 3) << 2;
                    va[i] = *(const float4*)(A  + (size_t)(m0 + r) * K + (kt + 1) * 16 + c4);
                    vb[i] = *(const float4*)(Bt + (size_t)(n0 + r) * K + (kt + 1) * 16 + c4);
                }
            }
            #pragma unroll
            for (int ks = 0; ks < 2; ks++) {
                const int k = ks * 8;
                uint32_t a[4][4], b[4][2];
                #pragma unroll
                for (int mf = 0; mf < 4; mf++) {
                    int r0 = wm * 64 + mf * 16;
                    a[mf][0] = __float_as_uint(AS(cur, k + tg,     r0 + gp));
                    a[mf][1] = __float_as_uint(AS(cur, k + tg,     r0 + gp + 8));
                    a[mf][2] = __float_as_uint(AS(cur, k + tg + 4, r0 + gp));
                    a[mf][3] = __float_as_uint(AS(cur, k + tg + 4, r0 + gp + 8));
                }
                #pragma unroll
                for (int nf = 0; nf < 4; nf++) {
                    int c0 = wn * 32 + nf * 8;
                    b[nf][0] = __float_as_uint(BS(cur, k + tg,     c0 + gp));
                    b[nf][1] = __float_as_uint(BS(cur, k + tg + 4, c0 + gp));
                }
                #pragma unroll
                for (int mf = 0; mf < 4; mf++)
                    #pragma unroll
                    for (int nf = 0; nf < 4; nf++)
                        mma_tf32(c[mf][nf], a[mf][0], a[mf][1], a[mf][2], a[mf][3],
                                 b[nf][0], b[nf][1]);
            }
            if (kt + 1 < KT) {
                int nxt = cur ^ 1;
                #pragma unroll
                for (int i = 0; i < 2; i++) {
                    int idx = tid + i * 256;
                    int r = idx >> 2, c4 = (idx & 3) << 2;
                    AS(nxt, c4 + 0, r) = to_tf32(va[i].x);
                    AS(nxt, c4 + 1, r) = to_tf32(va[i].y);
                    AS(nxt, c4 + 2, r) = to_tf32(va[i].z);
                    AS(nxt, c4 + 3, r) = to_tf32(va[i].w);
                    BS(nxt, c4 + 0, r) = to_tf32(vb[i].x);
                    BS(nxt, c4 + 1, r) = to_tf32(vb[i].y);
                    BS(nxt, c4 + 2, r) = to_tf32(vb[i].z);
                    BS(nxt, c4 + 3, r) = to_tf32(vb[i].w);
                }
                __syncthreads();
                cur = nxt;
            }
        }

        #pragma unroll
        for (int mf = 0; mf < 4; mf++) {
            #pragma unroll
            for (int nf = 0; nf < 4; nf++) {
                int col = n0 + wn * 32 + nf * 8 + 2 * tg;
                float bi0 = bias[col], bi1 = bias[col + 1];
                #pragma unroll
                for (int hh = 0; hh < 2; hh++) {
                    int row = m0 + wm * 64 + mf * 16 + gp + hh * 8;
                    float v0 = c[mf][nf][hh * 2 + 0] + bi0;
                    float v1 = c[mf][nf][hh * 2 + 1] + bi1;
                    if (MODE == 1) {
                        const float2 rv = *(const float2*)(res + (size_t)row * N + col);
                        v0 += rv.x; v1 += rv.y;
                    }
                    if (MODE == 2) { v0 = gelu_exact(v0); v1 = gelu_exact(v1); }
                    if (MODE == 0 || MODE == 2) { v0 = to_tf32(v0); v1 = to_tf32(v1); }
                    float2 o; o.x = v0; o.y = v1;
                    *(float2*)(C + (size_t)row * N + col) = o;
                }
            }
        }
    }
    #undef AS
    #undef BS
#endif
}

// ---------------- causal flash attention (unchanged; writes tf32-rounded y) ----------------
#define AT_STRIDE 76
#define AT_BUF    (64 * AT_STRIDE)
#define ATTN_SMEM ((4 * AT_BUF) * 4 + 2 * 64 * 4)

__global__ __launch_bounds__(256) void attn_kernel(
    const float* __restrict__ qkv, const int* __restrict__ amask,
    float* __restrict__ y)
{
    extern __shared__ float sm[];
    float* kb = sm;
    float* vb = sm + 2 * AT_BUF;
    int*   mk = (int*)(sm + 4 * AT_BUF);

    const int tid = threadIdx.x, lane = tid & 31, w = tid >> 5;
    const int gp = lane >> 2, tg = lane & 3;
    const int h = blockIdx.y;
    const int q0 = (gridDim.x - 1 - blockIdx.x) * 128;
    const int qw = q0 + w * 16;

    #pragma unroll
    for (int i = 0; i < 8; i++) {
        int idx = tid + i * 256;
        int r = idx >> 4, c4 = (idx & 15) << 2;
        const float4 v = *(const float4*)(qkv + (size_t)(q0 + r) * (3 * DM) + h * HDIM + c4);
        float* dst = (r < 64 ? (kb + AT_BUF) : (vb + AT_BUF)) + (r & 63) * AT_STRIDE + c4;
        *(float4*)dst = v;
    }

    {
        int r = tid >> 2, cg = (tid & 3) << 4;
        const float* gk = qkv + (size_t)r * (3 * DM) + DM + h * HDIM + cg;
        uint32_t dk = (uint32_t)__cvta_generic_to_shared(kb + r * AT_STRIDE + cg);
        uint32_t dv = (uint32_t)__cvta_generic_to_shared(vb + r * AT_STRIDE + cg);
        #pragma unroll
        for (int i = 0; i < 4; i++) {
            cp16(dk + i * 16, gk + i * 4);
            cp16(dv + i * 16, gk + DM + i * 4);
        }
        if (tid < 16) {
            uint32_t dm = (uint32_t)__cvta_generic_to_shared(mk + tid * 4);
            cp16(dm, amask + tid * 4);
        }
    }
    asm volatile("cp.async.commit_group;\n" ::: "memory");
    __syncthreads();

    uint32_t qa[8][4];
    {
        const float* st = (w < 4 ? (kb + AT_BUF) : (vb + AT_BUF));
        int r0 = (w * 16) & 63;
        #pragma unroll
        for (int ks = 0; ks < 8; ks++) {
            qa[ks][0] = to_tf32_u(st[(r0 + gp    ) * AT_STRIDE + ks * 8 + tg    ]);
            qa[ks][1] = to_tf32_u(st[(r0 + gp + 8) * AT_STRIDE + ks * 8 + tg    ]);
            qa[ks][2] = to_tf32_u(st[(r0 + gp    ) * AT_STRIDE + ks * 8 + tg + 4]);
            qa[ks][3] = to_tf32_u(st[(r0 + gp + 8) * AT_STRIDE + ks * 8 + tg + 4]);
        }
    }

    float m0 = -INFINITY, m1 = -INFINITY, l0 = 0.f, l1 = 0.f;
    float o[8][4];
    #pragma unroll
    for (int nf = 0; nf < 8; nf++)
        #pragma unroll
        for (int r = 0; r < 4; r++) o[nf][r] = 0.f;

    const int ktmax = (q0 + 127) >> 6;
    const int row0 = qw + gp, row1 = qw + gp + 8;
    int cur = 0;

    for (int kt = 0; kt <= ktmax; kt++) {
        asm volatile("cp.async.wait_group 0;\n" ::: "memory");
        __syncthreads();

        if (kt < ktmax) {
            int nb = cur ^ 1;
            int r = tid >> 2, cg = (tid & 3) << 4;
            const float* gk = qkv + (size_t)((kt + 1) * 64 + r) * (3 * DM) + DM + h * HDIM + cg;
            uint32_t dk = (uint32_t)__cvta_generic_to_shared(kb + nb * AT_BUF + r * AT_STRIDE + cg);
            uint32_t dv = (uint32_t)__cvta_generic_to_shared(vb + nb * AT_BUF + r * AT_STRIDE + cg);
            #pragma unroll
            for (int i = 0; i < 4; i++) {
                cp16(dk + i * 16, gk + i * 4);
                cp16(dv + i * 16, gk + DM + i * 4);
            }
            if (tid < 16) {
                uint32_t dm = (uint32_t)__cvta_generic_to_shared(mk + nb * 64 + tid * 4);
                cp16(dm, amask + (kt + 1) * 64 + tid * 4);
            }
            asm volatile("cp.async.commit_group;\n" ::: "memory");
        }

        const float* K = kb + cur * AT_BUF;
        const float* V = vb + cur * AT_BUF;
        const int*   M = mk + cur * 64;

        float sc[8][4];
        #pragma unroll
        for (int nf = 0; nf < 8; nf++)
            #pragma unroll
            for (int r = 0; r < 4; r++) sc[nf][r] = 0.f;

        #pragma unroll
        for (int ks = 0; ks < 8; ks++) {
            #pragma unroll
            for (int nf = 0; nf < 8; nf++) {
                uint32_t b0 = __float_as_uint(K[(nf * 8 + gp) * AT_STRIDE + ks * 8 + tg    ]);
                uint32_t b1 = __float_as_uint(K[(nf * 8 + gp) * AT_STRIDE + ks * 8 + tg + 4]);
                mma_tf32(sc[nf], qa[ks][0], qa[ks][1], qa[ks][2], qa[ks][3], b0, b1);
            }
        }

        float tm0 = -INFINITY, tm1 = -INFINITY;
        #pragma unroll
        for (int nf = 0; nf < 8; nf++) {
            int cl = nf * 8 + 2 * tg;
            int c  = kt * 64 + cl;
            bool mk0 = M[cl] != 0, mk1 = M[cl + 1] != 0;
            float s0 = sc[nf][0] * 0.125f, s1 = sc[nf][1] * 0.125f;
            float s2 = sc[nf][2] * 0.125f, s3 = sc[nf][3] * 0.125f;
            s0 = (c     <= row0 && mk0) ? s0 : -INFINITY;
            s1 = (c + 1 <= row0 && mk1) ? s1 : -INFINITY;
            s2 = (c     <= row1 && mk0) ? s2 : -INFINITY;
            s3 = (c + 1 <= row1 && mk1) ? s3 : -INFINITY;
            sc[nf][0] = s0; sc[nf][1] = s1; sc[nf][2] = s2; sc[nf][3] = s3;
            tm0 = fmaxf(tm0, fmaxf(s0, s1));
            tm1 = fmaxf(tm1, fmaxf(s2, s3));
        }
        tm0 = fmaxf(tm0, __shfl_xor_sync(0xffffffffu, tm0, 1));
        tm0 = fmaxf(tm0, __shfl_xor_sync(0xffffffffu, tm0, 2));
        tm1 = fmaxf(tm1, __shfl_xor_sync(0xffffffffu, tm1, 1));
        tm1 = fmaxf(tm1, __shfl_xor_sync(0xffffffffu, tm1, 2));

        float nm0 = fmaxf(m0, tm0), nm1 = fmaxf(m1, tm1);
        float ne0 = fmaxf(nm0, -1e30f), ne1 = fmaxf(nm1, -1e30f);
        float al0 = __expf(m0 - ne0), al1 = __expf(m1 - ne1);
        m0 = nm0; m1 = nm1;

        float ps0 = 0.f, ps1 = 0.f;
        #pragma unroll
        for (int nf = 0; nf < 8; nf++) {
            float p0 = __expf(sc[nf][0] - ne0);
            float p1 = __expf(sc[nf][1] - ne0);
            float p2 = __expf(sc[nf][2] - ne1);
            float p3 = __expf(sc[nf][3] - ne1);
            sc[nf][0] = p0; sc[nf][1] = p1; sc[nf][2] = p2; sc[nf][3] = p3;
            ps0 += p0 + p1; ps1 += p2 + p3;
        }
        ps0 += __shfl_xor_sync(0xffffffffu, ps0, 1);
        ps0 += __shfl_xor_sync(0xffffffffu, ps0, 2);
        ps1 += __shfl_xor_sync(0xffffffffu, ps1, 1);
        ps1 += __shfl_xor_sync(0xffffffffu, ps1, 2);
        l0 = l0 * al0 + ps0;
        l1 = l1 * al1 + ps1;

        #pragma unroll
        for (int nf = 0; nf < 8; nf++) {
            o[nf][0] *= al0; o[nf][1] *= al0;
            o[nf][2] *= al1; o[nf][3] *= al1;
        }

        const int src0 = (lane & ~3) | (tg >> 1);
        const int src1 = src0 + 2;
        const bool odd = (tg & 1) != 0;
        #pragma unroll
        for (int ks = 0; ks < 8; ks++) {
            float e00 = __shfl_sync(0xffffffffu, sc[ks][0], src0);
            float e01 = __shfl_sync(0xffffffffu, sc[ks][1], src0);
            float e10 = __shfl_sync(0xffffffffu, sc[ks][2], src0);
            float e11 = __shfl_sync(0xffffffffu, sc[ks][3], src0);
            float f00 = __shfl_sync(0xffffffffu, sc[ks][0], src1);
            float f01 = __shfl_sync(0xffffffffu, sc[ks][1], src1);
            float f10 = __shfl_sync(0xffffffffu, sc[ks][2], src1);
            float f11 = __shfl_sync(0xffffffffu, sc[ks][3], src1);
            uint32_t pa0 = to_tf32_u(odd ? e01 : e00);
            uint32_t pa1 = to_tf32_u(odd ? e11 : e10);
            uint32_t pa2 = to_tf32_u(odd ? f01 : f00);
            uint32_t pa3 = to_tf32_u(odd ? f11 : f10);
            #pragma unroll
            for (int nf = 0; nf < 8; nf++) {
                uint32_t b0 = __float_as_uint(V[(ks * 8 + tg    ) * AT_STRIDE + nf * 8 + gp]);
                uint32_t b1 = __float_as_uint(V[(ks * 8 + tg + 4) * AT_STRIDE + nf * 8 + gp]);
                mma_tf32(o[nf], pa0, pa1, pa2, pa3, b0, b1);
            }
        }
        cur ^= 1;
    }

    float il0 = 1.0f / fmaxf(l0, 1e-30f);
    float il1 = 1.0f / fmaxf(l1, 1e-30f);
    #pragma unroll
    for (int nf = 0; nf < 8; nf++) {
        int col = h * HDIM + nf * 8 + 2 * tg;
        float2 v0; v0.x = to_tf32(o[nf][0] * il0); v0.y = to_tf32(o[nf][1] * il0);
        *(float2*)(y + (size_t)row0 * DM + col) = v0;
        float2 v1; v1.x = to_tf32(o[nf][2] * il1); v1.y = to_tf32(o[nf][3] * il1);
        *(float2*)(y + (size_t)row1 * DM + col) = v1;
    }
}

// ---------------- launcher ----------------
extern "C" void kernel_launch(void* const* d_in, const int* in_sizes, int n_in,
                              void* d_out, int out_size)
{
    const float* x     = (const float*)d_in[0];
    const int*   amask = (const int*)  d_in[1];
    const float* ln1g  = (const float*)d_in[2];
    const float* ln1b  = (const float*)d_in[3];
    const float* Wqkv  = (const float*)d_in[4];
    const float* bqkv  = (const float*)d_in[5];
    const float* Wo    = (const float*)d_in[6];
    const float* bo    = (const float*)d_in[7];
    const float* ln2g  = (const float*)d_in[8];
    const float* ln2b  = (const float*)d_in[9];
    const float* W1    = (const float*)d_in[10];
    const float* b1    = (const float*)d_in[11];
    const float* W2    = (const float*)d_in[12];
    const float* b2    = (const float*)d_in[13];
    float* out = (float*)d_out;

    void *p_ln, *p_qkv, *p_y, *p_x2, *p_ff;
    void *p_wqkv, *p_wo, *p_w1, *p_w2;
    cudaGetSymbolAddress(&p_ln,   g_ln);
    cudaGetSymbolAddress(&p_qkv,  g_qkv);
    cudaGetSymbolAddress(&p_y,    g_y);
    cudaGetSymbolAddress(&p_x2,   g_x2);
    cudaGetSymbolAddress(&p_ff,   g_ff);
    cudaGetSymbolAddress(&p_wqkv, g_wt_qkv);
    cudaGetSymbolAddress(&p_wo,   g_wt_o);
    cudaGetSymbolAddress(&p_w1,   g_wt_1);
    cudaGetSymbolAddress(&p_w2,   g_wt_2);

    cudaFuncSetAttribute(attn_kernel,
        cudaFuncAttributeMaxDynamicSharedMemorySize, ATTN_SMEM);
    cudaFuncSetAttribute(gemm_any<0>,
        cudaFuncAttributeMaxDynamicSharedMemorySize, G_SMEM);
    cudaFuncSetAttribute(gemm_any<1>,
        cudaFuncAttributeMaxDynamicSharedMemorySize, G_SMEM);
    cudaFuncSetAttribute(gemm_any<2>,
        cudaFuncAttributeMaxDynamicSharedMemorySize, G_SMEM);

    // 0. weight transposes (tf32-rounded, [N,K])
    transpose_kernel<<<dim3(3 * DM / 32, DM / 32), 256>>>(Wqkv, (float*)p_wqkv, DM, 3 * DM);
    transpose_kernel<<<dim3(DM / 32, DM / 32),     256>>>(Wo,   (float*)p_wo,   DM, DM);
    transpose_kernel<<<dim3(DFF / 32, DM / 32),    256>>>(W1,   (float*)p_w1,   DM, DFF);
    transpose_kernel<<<dim3(DM / 32, DFF / 32),    256>>>(W2,   (float*)p_w2,   DFF, DM);

    // 1. LN1
    ln_kernel<<<T_SEQ, 256>>>(x, ln1g, ln1b, (float*)p_ln);
    // 2. QKV
    gemm_any<0><<<dim3(12, 32), 256, G_SMEM>>>((float*)p_ln, (float*)p_wqkv, bqkv, nullptr,
                                               (float*)p_qkv, T_SEQ, 3 * DM, DM);
    // 3. attention
    attn_kernel<<<dim3(32, 16), 256, ATTN_SMEM>>>((float*)p_qkv, amask, (float*)p_y);
    // 4. x2 = x + y @ W_o + b_o
    gemm_any<1><<<dim3(4, 32), 256, G_SMEM>>>((float*)p_y, (float*)p_wo, bo, x,
                                              (float*)p_x2, T_SEQ, DM, DM);
    // 5. LN2
    ln_kernel<<<T_SEQ, 256>>>((float*)p_x2, ln2g, ln2b, (float*)p_ln);
    // 6. ff = gelu(h2 @ W1 + b1)
    gemm_any<2><<<dim3(16, 32), 256, G_SMEM>>>((float*)p_ln, (float*)p_w1, b1, nullptr,
                                               (float*)p_ff, T_SEQ, DFF, DM);
    // 7. out = x2 + ff @ W2 + b2
    gemm_any<1><<<dim3(4, 32), 256, G_SMEM>>>((float*)p_ff, (float*)p_w2, b2, (float*)p_x2,
                                              out, T_SEQ, DM, DFF);
}

// round 7
// speedup vs baseline: 2.4258x; 1.3039x over previous
#include <cuda_runtime.h>
#include <cuda_bf16.h>
#include <cstdint>
#include <math.h>

#define T_SEQ   4096
#define DM      1024
#define DFF     4096
#define NHEADS  16
#define HDIM    64
#define LN_EPS  1e-5f

// ---- arch-specific feature gate: tcgen05 only exists on sm_10xa/f targets ----
#if defined(__CUDA_ARCH__)
#  if defined(__CUDA_ARCH_FEAT_SM103_ALL) || defined(__CUDA_ARCH_FEAT_SM100_ALL) || defined(__CUDA_ARCH_FEAT_SM101_ALL)
#    define GEMM_TC 1
#  elif defined(__CUDA_ARCH_SPECIFIC__)
#    define GEMM_TC ((__CUDA_ARCH_SPECIFIC__ >= 1000) ? 1 : 0)
#  elif defined(__CUDA_ARCH_FAMILY_SPECIFIC__)
#    define GEMM_TC ((__CUDA_ARCH_FAMILY_SPECIFIC__ >= 1000) ? 1 : 0)
#  else
#    define GEMM_TC 0
#  endif
#else
#  define GEMM_TC 0
#endif

// ---------------- scratch (static device globals; no allocation) ----------------
static __device__ float g_ln [T_SEQ * DM];
static __device__ float g_y  [T_SEQ * DM];
static __device__ float g_x2 [T_SEQ * DM];
static __device__ float g_ff [T_SEQ * DFF];
// transposed (tf32-rounded) weights, [N, K] K-major
static __device__ float g_wt_qkv[3 * DM * DM];
static __device__ float g_wt_o  [DM * DM];
static __device__ float g_wt_1  [DFF * DM];
static __device__ float g_wt_2  [DM * DFF];
// bf16 attention operands written by the QKV GEMM epilogue
static __device__ __nv_bfloat16 g_q16[NHEADS * T_SEQ * HDIM];   // [h][t][d], pre-scaled 1/8
static __device__ __nv_bfloat16 g_k16[NHEADS * T_SEQ * HDIM];   // [h][t][d]
static __device__ uint32_t      g_v16[NHEADS * (T_SEQ/2) * HDIM]; // [h][t/2][d] = {lo:t even, hi:t odd}

// ---------------- helpers ----------------
__device__ __forceinline__ float to_tf32(float x) {
    uint32_t u;
    asm("cvt.rna.tf32.f32 %0, %1;" : "=r"(u) : "f"(x));
    return __uint_as_float(u);
}

__device__ __forceinline__ uint32_t packbf(float hi, float lo) {
    uint32_t r;
    asm("cvt.rn.bf16x2.f32 %0, %1, %2;" : "=r"(r) : "f"(hi), "f"(lo));
    return r;
}

__device__ __forceinline__ void mma_tf32(float* c,
    uint32_t a0, uint32_t a1, uint32_t a2, uint32_t a3,
    uint32_t b0, uint32_t b1)
{
    asm volatile(
        "mma.sync.aligned.m16n8k8.row.col.f32.tf32.tf32.f32 "
        "{%0,%1,%2,%3}, {%4,%5,%6,%7}, {%8,%9}, {%0,%1,%2,%3};\n"
        : "+f"(c[0]), "+f"(c[1]), "+f"(c[2]), "+f"(c[3])
        : "r"(a0), "r"(a1), "r"(a2), "r"(a3), "r"(b0), "r"(b1));
}

__device__ __forceinline__ void mma_bf16(float* c,
    uint32_t a0, uint32_t a1, uint32_t a2, uint32_t a3,
    uint32_t b0, uint32_t b1)
{
    asm volatile(
        "mma.sync.aligned.m16n8k16.row.col.f32.bf16.bf16.f32 "
        "{%0,%1,%2,%3}, {%4,%5,%6,%7}, {%8,%9}, {%0,%1,%2,%3};\n"
        : "+f"(c[0]), "+f"(c[1]), "+f"(c[2]), "+f"(c[3])
        : "r"(a0), "r"(a1), "r"(a2), "r"(a3), "r"(b0), "r"(b1));
}

__device__ __forceinline__ void cp16(uint32_t dst, const void* src) {
    asm volatile("cp.async.ca.shared.global [%0], [%1], 16;\n"
                 :: "r"(dst), "l"(src));
}

__device__ __forceinline__ float gelu_exact(float v) {
    return 0.5f * v * (1.0f + erff(v * 0.70710678118654752440f));
}

// ---------------- weight transpose + tf32 round ----------------
__global__ __launch_bounds__(256) void transpose_kernel(
    const float* __restrict__ in, float* __restrict__ out, int R, int C)
{
    __shared__ float t[32][33];
    int bx = blockIdx.x * 32, by = blockIdx.y * 32;
    int x = threadIdx.x & 31, y = threadIdx.x >> 5;
    #pragma unroll
    for (int i = 0; i < 32; i += 8)
        t[y + i][x] = in[(size_t)(by + y + i) * C + bx + x];
    __syncthreads();
    #pragma unroll
    for (int i = 0; i < 32; i += 8)
        out[(size_t)(bx + y + i) * R + by + x] = to_tf32(t[x][y + i]);
}

// ---------------- LayerNorm (writes tf32-rounded output) ----------------
__global__ __launch_bounds__(256) void ln_kernel(
    const float* __restrict__ x, const float* __restrict__ g,
    const float* __restrict__ b, float* __restrict__ out)
{
    int row = blockIdx.x;
    int tid = threadIdx.x;
    const float4 v = ((const float4*)(x + (size_t)row * DM))[tid];
    float s  = v.x + v.y + v.z + v.w;
    float sq = v.x * v.x + v.y * v.y + v.z * v.z + v.w * v.w;
    #pragma unroll
    for (int o = 16; o; o >>= 1) {
        s  += __shfl_xor_sync(0xffffffffu, s,  o);
        sq += __shfl_xor_sync(0xffffffffu, sq, o);
    }
    __shared__ float ss[8], ssq[8];
    __shared__ float mean_s, inv_s;
    int w = tid >> 5, l = tid & 31;
    if (l == 0) { ss[w] = s; ssq[w] = sq; }
    __syncthreads();
    if (tid == 0) {
        float st = 0.f, sqt = 0.f;
        #pragma unroll
        for (int i = 0; i < 8; i++) { st += ss[i]; sqt += ssq[i]; }
        float mean = st * (1.0f / DM);
        float var  = sqt * (1.0f / DM) - mean * mean;
        mean_s = mean;
        inv_s  = rsqrtf(var + LN_EPS);
    }
    __syncthreads();
    float mean = mean_s, inv = inv_s;
    const float4 gv = ((const float4*)g)[tid];
    const float4 bv = ((const float4*)b)[tid];
    float4 o;
    o.x = to_tf32((v.x - mean) * inv * gv.x + bv.x);
    o.y = to_tf32((v.y - mean) * inv * gv.y + bv.y);
    o.z = to_tf32((v.z - mean) * inv * gv.z + bv.z);
    o.w = to_tf32((v.w - mean) * inv * gv.w + bv.w);
    ((float4*)(out + (size_t)row * DM))[tid] = o;
}

// ---------------- unified GEMM: C[M,N] = A[M,K] @ Bt[N,K]^T + epilogue --------
// Tile 256x256, 256 threads. grid = (N/256, M/256).
// TC path: tcgen05 SS tf32, BK=32, 3-stage ring, 2 TMEM accumulators (M=2x128).
// Fallback: proven mma.sync 128x128 body, 2x2 subtiles.
// MODE 1: +bias+res (fp32)  MODE 2: gelu(+bias), round  MODE 3: QKV -> bf16 buffers
#define GS        3
#define G_TILE_AB 32768
#define G_STAGE   (2 * G_TILE_AB)           // 65536
#define G_BASE    1024
#define G_SMEM    (G_BASE + GS * G_STAGE)   // 197632

#if GEMM_TC
__device__ __forceinline__ bool elect_one() {
    uint32_t pred;
    asm volatile(
        "{\n\t.reg .pred p;\n\t"
        "elect.sync _|p, 0xFFFFFFFF;\n\t"
        "selp.b32 %0, 1, 0, p;\n\t}"
        : "=r"(pred));
    return pred != 0;
}
__device__ __forceinline__ uint64_t make_desc(uint32_t addr) {
    const uint64_t base = (2ULL << 61) | (1ULL << 46) | (64ULL << 32) | (1ULL << 16);
    return base | ((uint64_t)(addr >> 4) & 0x3FFF);
}
__device__ __forceinline__ void tc_mma_tf32_ss(uint32_t d, uint64_t ad, uint64_t bd,
                                               uint32_t idesc, bool acc)
{
    uint32_t en = acc ? 1u : 0u;
    asm volatile(
        "{\n\t.reg .pred p;\n\t"
        "setp.ne.u32 p, %4, 0;\n\t"
        "tcgen05.mma.cta_group::1.kind::tf32 [%0], %1, %2, %3, {%5, %5, %5, %5}, p;\n\t}"
        :: "r"(d), "l"(ad), "l"(bd), "r"(idesc), "r"(en), "r"(0u)
        : "memory");
}
#define MBAR_INIT(a, c) \
    asm volatile("mbarrier.init.shared.b64 [%0], %1;" :: "r"(a), "r"(c) : "memory")
#define MBAR_WAIT(a, par) do { \
    uint32_t _m = (a), _p = (par), _d; \
    asm volatile("{\n\t.reg .pred p;\n\t" \
        "mbarrier.try_wait.parity.acquire.cta.shared::cta.b64 p, [%1], %2;\n\t" \
        "selp.b32 %0, 1, 0, p;\n\t}" : "=r"(_d) : "r"(_m), "r"(_p) : "memory"); \
    if (!_d) { \
        asm volatile("{\n\t.reg .pred P1;\n\t" \
            "WL_%=:\n\t" \
            "mbarrier.try_wait.parity.acquire.cta.shared::cta.b64 P1, [%0], %1, 0x989680;\n\t" \
            "@P1 bra.uni WD_%=;\n\t" \
            "bra.uni WL_%=;\n\t" \
            "WD_%=:\n\t}" :: "r"(_m), "r"(_p) : "memory"); \
    } \
} while (0)
#endif  // GEMM_TC

// epilogue write helper for MODE 3 (pair of adjacent columns, one row)
__device__ __forceinline__ void qkv_write_pair(int n, int row, float v0, float v1) {
    if (n < 1024) {
        int hd = n >> 6, d = n & 63;
        ((uint32_t*)g_q16)[(((size_t)hd * T_SEQ + row) * 64 + d) >> 1]
            = packbf(v1 * 0.125f, v0 * 0.125f);
    } else if (n < 2048) {
        int hd = (n - 1024) >> 6, d = (n - 1024) & 63;
        ((uint32_t*)g_k16)[(((size_t)hd * T_SEQ + row) * 64 + d) >> 1]
            = packbf(v1, v0);
    } else {
        int hd = (n - 2048) >> 6, d = (n - 2048) & 63;
        __nv_bfloat16* vp = (__nv_bfloat16*)g_v16;
        size_t wi = ((size_t)hd * (T_SEQ / 2) + (row >> 1)) * 64 + d;
        vp[wi * 2 + (row & 1)]       = __float2bfloat16(v0);
        vp[(wi + 1) * 2 + (row & 1)] = __float2bfloat16(v1);
    }
}

template<int MODE>
__global__ __launch_bounds__(256)
void gemm_any(const float* __restrict__ A, const float* __restrict__ Bt,
              const float* __restrict__ bias, const float* __restrict__ res,
              float* __restrict__ C, int M, int N, int K)
{
    extern __shared__ __align__(1024) char gsm[];
    const int tid = threadIdx.x, wid = tid >> 5, lane = tid & 31;

#if GEMM_TC
    // ================= tcgen05 path (256x256 tile) =================
    const int m0 = blockIdx.y * 256, n0 = blockIdx.x * 256;
    const uint32_t sb = (uint32_t)__cvta_generic_to_shared(gsm);
    const uint32_t mb0 = sb + 16, mb1 = sb + 24;

    if (wid == 0) {
        asm volatile("tcgen05.alloc.cta_group::1.sync.aligned.shared::cta.b32 [%0], %1;"
                     :: "r"(sb), "r"(512u) : "memory");
        asm volatile("tcgen05.relinquish_alloc_permit.cta_group::1.sync.aligned;");
    }
    if (tid == 0) { MBAR_INIT(mb0, 1); MBAR_INIT(mb1, 1); }
    __syncthreads();
    uint32_t tb;
    asm volatile("ld.shared.b32 %0, [%1];" : "=r"(tb) : "r"(sb));

    const int KT = K >> 5;

    auto fill = [&](int slot, int ktile) {
        uint32_t s = sb + G_BASE + slot * G_STAGE;
        const float* Ap = A  + (size_t)m0 * K + ktile * 32;
        const float* Bp = Bt + (size_t)n0 * K + ktile * 32;
        #pragma unroll
        for (int i = 0; i < 8; i++) {
            int idx = tid + i * 256;          // 0..2047
            int r = idx >> 3, ch = (idx & 7) * 16;
            uint32_t byte = (uint32_t)(r * 128 + ch);
            uint32_t sw = byte ^ ((byte >> 3) & 0x70);
            cp16(s + sw,             Ap + (size_t)r * K + (ch >> 2));
            cp16(s + G_TILE_AB + sw, Bp + (size_t)r * K + (ch >> 2));
        }
    };

    #pragma unroll
    for (int st = 0; st < GS - 1; st++) {
        fill(st, st);
        asm volatile("cp.async.commit_group;" ::: "memory");
    }

    // idesc: accum F32, atype=btype=TF32(2), N=256, M=128 (per accumulator)
    const uint32_t idesc = (1u << 4) | (2u << 7) | (2u << 10)
                         | (32u << 17) | (8u << 24);

    int ph0 = 0, ph1 = 0;
    for (int kt = 0; kt < KT; kt++) {
        asm volatile("cp.async.wait_group %0;" :: "n"(GS - 2) : "memory");
        asm volatile("fence.proxy.async.shared::cta;" ::: "memory");
        __syncthreads();

        if (wid == 0 && elect_one()) {
            uint32_t s = sb + G_BASE + (kt % GS) * G_STAGE;
            uint64_t ad = make_desc(s);
            uint64_t bd = make_desc(s + G_TILE_AB);
            #pragma unroll
            for (int ks = 0; ks < 4; ks++) {
                bool acc = (kt > 0) || (ks > 0);
                tc_mma_tf32_ss(tb,       ad + ks * 2,        bd + ks * 2, idesc, acc);
                tc_mma_tf32_ss(tb + 256, ad + 1024 + ks * 2, bd + ks * 2, idesc, acc);
            }
            uint32_t mb = (kt & 1) ? mb1 : mb0;
            asm volatile(
                "tcgen05.commit.cta_group::1.mbarrier::arrive::one.shared::cluster.b64 [%0];"
                :: "r"(mb) : "memory");
        }

        if (kt >= 1) {
            if ((kt - 1) & 1) { MBAR_WAIT(mb1, ph1); ph1 ^= 1; }
            else              { MBAR_WAIT(mb0, ph0); ph0 ^= 1; }
        }
        if (kt + GS - 1 < KT) fill((kt + GS - 1) % GS, kt + GS - 1);
        asm volatile("cp.async.commit_group;" ::: "memory");
    }

    if ((KT - 1) & 1) { MBAR_WAIT(mb1, ph1); }
    else              { MBAR_WAIT(mb0, ph0); }
    asm volatile("tcgen05.fence::after_thread_sync;" ::: "memory");

    {
        const int row = m0 + ((wid < 4) ? wid * 32 : 128 + (wid - 4) * 32) + lane;
        const uint32_t dbase = tb + ((wid < 4) ? 0u : 256u);
        #pragma unroll
        for (int c0 = 0; c0 < 256; c0 += 32) {
            float d[32];
            asm volatile(
                "tcgen05.ld.sync.aligned.32x32b.x32.b32 "
                "{%0,%1,%2,%3,%4,%5,%6,%7,%8,%9,%10,%11,%12,%13,%14,%15,"
                "%16,%17,%18,%19,%20,%21,%22,%23,%24,%25,%26,%27,%28,%29,%30,%31}, [%32];"
                : "=f"(d[0]),  "=f"(d[1]),  "=f"(d[2]),  "=f"(d[3]),
                  "=f"(d[4]),  "=f"(d[5]),  "=f"(d[6]),  "=f"(d[7]),
                  "=f"(d[8]),  "=f"(d[9]),  "=f"(d[10]), "=f"(d[11]),
                  "=f"(d[12]), "=f"(d[13]), "=f"(d[14]), "=f"(d[15]),
                  "=f"(d[16]), "=f"(d[17]), "=f"(d[18]), "=f"(d[19]),
                  "=f"(d[20]), "=f"(d[21]), "=f"(d[22]), "=f"(d[23]),
                  "=f"(d[24]), "=f"(d[25]), "=f"(d[26]), "=f"(d[27]),
                  "=f"(d[28]), "=f"(d[29]), "=f"(d[30]), "=f"(d[31])
                : "r"(dbase + c0));
            asm volatile("tcgen05.wait::ld.sync.aligned;" ::: "memory");

            #pragma unroll
            for (int c = 0; c < 32; c += 4) {
                const int n = n0 + c0 + c;
                const float4 bv = *(const float4*)(bias + n);
                float4 v;
                v.x = d[c + 0] + bv.x; v.y = d[c + 1] + bv.y;
                v.z = d[c + 2] + bv.z; v.w = d[c + 3] + bv.w;
                if (MODE == 3) {
                    qkv_write_pair(n,     row, v.x, v.y);
                    qkv_write_pair(n + 2, row, v.z, v.w);
                } else {
                    if (MODE == 1) {
                        const float4 rv = *(const float4*)(res + (size_t)row * N + n);
                        v.x += rv.x; v.y += rv.y; v.z += rv.z; v.w += rv.w;
                    }
                    if (MODE == 2) {
                        v.x = to_tf32(gelu_exact(v.x)); v.y = to_tf32(gelu_exact(v.y));
                        v.z = to_tf32(gelu_exact(v.z)); v.w = to_tf32(gelu_exact(v.w));
                    }
                    *(float4*)(C + (size_t)row * N + n) = v;
                }
            }
        }
    }

    __syncthreads();
    if (tid == 0) {
        asm volatile("mbarrier.inval.shared.b64 [%0];" :: "r"(mb0) : "memory");
        asm volatile("mbarrier.inval.shared.b64 [%0];" :: "r"(mb1) : "memory");
    }
    __syncthreads();
    if (wid == 0)
        asm volatile("tcgen05.dealloc.cta_group::1.sync.aligned.b32 %0, %1;"
                     :: "r"(tb), "r"(512u));

#else
    // ================= mma.sync fallback: 2x2 subtiles of 128x128 =================
    float* As = (float*)gsm;
    float* Bs = As + 2 * 16 * 132;
    #define AS(buf, k, m) As[((buf) * 16 + (k)) * 132 + (m)]
    #define BS(buf, k, n) Bs[((buf) * 16 + (k)) * 132 + (n)]

    const int wm = wid >> 2, wn = wid & 3;
    const int gp = lane >> 2, tg = lane & 3;

    for (int mi = 0; mi < 2; mi++)
    for (int ni = 0; ni < 2; ni++) {
        const int m0 = blockIdx.y * 256 + mi * 128;
        const int n0 = blockIdx.x * 256 + ni * 128;

        float c[4][4][4];
        #pragma unroll
        for (int i = 0; i < 4; i++)
            #pragma unroll
            for (int j = 0; j < 4; j++)
                #pragma unroll
                for (int r = 0; r < 4; r++) c[i][j][r] = 0.f;

        const int KT = K >> 4;
        float4 va[2], vb[2];

        __syncthreads();
        #pragma unroll
        for (int i = 0; i < 2; i++) {
            int idx = tid + i * 256;
            int r = idx >> 2, c4 = (idx & 3) << 2;
            va[i] = *(const float4*)(A  + (size_t)(m0 + r) * K + c4);
            vb[i] = *(const float4*)(Bt + (size_t)(n0 + r) * K + c4);
        }
        #pragma unroll
        for (int i = 0; i < 2; i++) {
            int idx = tid + i * 256;
            int r = idx >> 2, c4 = (idx & 3) << 2;
            AS(0, c4 + 0, r) = to_tf32(va[i].x);
            AS(0, c4 + 1, r) = to_tf32(va[i].y);
            AS(0, c4 + 2, r) = to_tf32(va[i].z);
            AS(0, c4 + 3, r) = to_tf32(va[i].w);
            BS(0, c4 + 0, r) = to_tf32(vb[i].x);
            BS(0, c4 + 1, r) = to_tf32(vb[i].y);
            BS(0, c4 + 2, r) = to_tf32(vb[i].z);
            BS(0, c4 + 3, r) = to_tf32(vb[i].w);
        }
        __syncthreads();

        int cur = 0;
        for (int kt = 0; kt < KT; kt++) {
            if (kt + 1 < KT) {
                #pragma unroll
                for (int i = 0; i < 2; i++) {
                    int idx = tid + i * 256;
                    int r = idx >> 2, c4 = (idx & 3) << 2;
                    va[i] = *(const float4*)(A  + (size_t)(m0 + r) * K + (kt + 1) * 16 + c4);
                    vb[i] = *(const float4*)(Bt + (size_t)(n0 + r) * K + (kt + 1) * 16 + c4);
                }
            }
            #pragma unroll
            for (int ks = 0; ks < 2; ks++) {
                const int k = ks * 8;
                uint32_t a[4][4], b[4][2];
                #pragma unroll
                for (int mf = 0; mf < 4; mf++) {
                    int r0 = wm * 64 + mf * 16;
                    a[mf][0] = __float_as_uint(AS(cur, k + tg,     r0 + gp));
                    a[mf][1] = __float_as_uint(AS(cur, k + tg,     r0 + gp + 8));
                    a[mf][2] = __float_as_uint(AS(cur, k + tg + 4, r0 + gp));
                    a[mf][3] = __float_as_uint(AS(cur, k + tg + 4, r0 + gp + 8));
                }
                #pragma unroll
                for (int nf = 0; nf < 4; nf++) {
                    int c0 = wn * 32 + nf * 8;
                    b[nf][0] = __float_as_uint(BS(cur, k + tg,     c0 + gp));
                    b[nf][1] = __float_as_uint(BS(cur, k + tg + 4, c0 + gp));
                }
                #pragma unroll
                for (int mf = 0; mf < 4; mf++)
                    #pragma unroll
                    for (int nf = 0; nf < 4; nf++)
                        mma_tf32(c[mf][nf], a[mf][0], a[mf][1], a[mf][2], a[mf][3],
                                 b[nf][0], b[nf][1]);
            }
            if (kt + 1 < KT) {
                int nxt = cur ^ 1;
                #pragma unroll
                for (int i = 0; i < 2; i++) {
                    int idx = tid + i * 256;
                    int r = idx >> 2, c4 = (idx & 3) << 2;
                    AS(nxt, c4 + 0, r) = to_tf32(va[i].x);
                    AS(nxt, c4 + 1, r) = to_tf32(va[i].y);
                    AS(nxt, c4 + 2, r) = to_tf32(va[i].z);
                    AS(nxt, c4 + 3, r) = to_tf32(va[i].w);
                    BS(nxt, c4 + 0, r) = to_tf32(vb[i].x);
                    BS(nxt, c4 + 1, r) = to_tf32(vb[i].y);
                    BS(nxt, c4 + 2, r) = to_tf32(vb[i].z);
                    BS(nxt, c4 + 3, r) = to_tf32(vb[i].w);
                }
                __syncthreads();
                cur = nxt;
            }
        }

        #pragma unroll
        for (int mf = 0; mf < 4; mf++) {
            #pragma unroll
            for (int nf = 0; nf < 4; nf++) {
                int col = n0 + wn * 32 + nf * 8 + 2 * tg;
                float bi0 = bias[col], bi1 = bias[col + 1];
                #pragma unroll
                for (int hh = 0; hh < 2; hh++) {
                    int row = m0 + wm * 64 + mf * 16 + gp + hh * 8;
                    float v0 = c[mf][nf][hh * 2 + 0] + bi0;
                    float v1 = c[mf][nf][hh * 2 + 1] + bi1;
                    if (MODE == 3) {
                        qkv_write_pair(col, row, v0, v1);
                    } else {
                        if (MODE == 1) {
                            const float2 rv = *(const float2*)(res + (size_t)row * N + col);
                            v0 += rv.x; v1 += rv.y;
                        }
                        if (MODE == 2) {
                            v0 = to_tf32(gelu_exact(v0));
                            v1 = to_tf32(gelu_exact(v1));
                        }
                        float2 o; o.x = v0; o.y = v1;
                        *(float2*)(C + (size_t)row * N + col) = o;
                    }
                }
            }
        }
    }
    #undef AS
    #undef BS
#endif
}

// ---------------- causal flash attention, bf16 m16n8k16 ----------------
// grid (32 qtiles, 16 heads), 256 threads (8 warps), 128-q x 64-key tiles.
// Q pre-scaled by 1/8 in QKV epilogue. P->A frags via pack (C-layout == A-layout).
// smem words: Qs[128][36] | Ks 2x[64][36] | Vs 2x[32][72] | msk 2x[64]
#define AQ_OFF  0
#define AK_OFF  4608
#define AV_OFF  9216
#define AM_OFF  13824
#define ATTN_SMEM ((13824 + 128) * 4)

__global__ __launch_bounds__(256) void attn_kernel(
    const int* __restrict__ amask, float* __restrict__ y)
{
    extern __shared__ uint32_t shw[];
    uint32_t* Qs = shw + AQ_OFF;
    uint32_t* Ks = shw + AK_OFF;
    uint32_t* Vs = shw + AV_OFF;
    int*      mk = (int*)(shw + AM_OFF);

    const int tid = threadIdx.x, lane = tid & 31, w = tid >> 5;
    const int gp = lane >> 2, tg = lane & 3;
    const int h = blockIdx.y;
    const int q0 = (gridDim.x - 1 - blockIdx.x) * 128;
    const int qw = q0 + w * 16;

    // ---- stage Q (bf16, pre-scaled) ----
    {
        const __nv_bfloat16* qb = g_q16 + ((size_t)h * T_SEQ + q0) * 64;
        #pragma unroll
        for (int i = 0; i < 4; i++) {
            int idx = tid + i * 256;
            int r = idx >> 3, ch = idx & 7;
            cp16((uint32_t)__cvta_generic_to_shared(Qs + r * 36 + ch * 4),
                 qb + (size_t)r * 64 + ch * 8);
        }
    }
    asm volatile("cp.async.commit_group;" ::: "memory");

    auto fill_kv = [&](int buf, int kt) {
        const __nv_bfloat16* kbs = g_k16 + ((size_t)h * T_SEQ + kt * 64) * 64;
        #pragma unroll
        for (int i = 0; i < 2; i++) {
            int idx = tid + i * 256;
            int r = idx >> 3, ch = idx & 7;
            cp16((uint32_t)__cvta_generic_to_shared(Ks + buf * 2304 + r * 36 + ch * 4),
                 kbs + (size_t)r * 64 + ch * 8);
        }
        const uint32_t* vbs = g_v16 + ((size_t)h * (T_SEQ / 2) + kt * 32) * 64;
        #pragma unroll
        for (int i = 0; i < 2; i++) {
            int idx = tid + i * 256;
            int pr = idx >> 4, ch = idx & 15;
            cp16((uint32_t)__cvta_generic_to_shared(Vs + buf * 2304 + pr * 72 + ch * 4),
                 vbs + (size_t)pr * 64 + ch * 4);
        }
        if (tid < 16)
            cp16((uint32_t)__cvta_generic_to_shared(mk + buf * 64 + tid * 4),
                 amask + kt * 64 + tid * 4);
    };

    fill_kv(0, 0);
    asm volatile("cp.async.commit_group;" ::: "memory");
    asm volatile("cp.async.wait_group 0;" ::: "memory");
    __syncthreads();

    // ---- Q fragments (m16n8k16 A layout; word = 2 dims) ----
    uint32_t qa[4][4];
    {
        int r0 = w * 16;
        #pragma unroll
        for (int ks = 0; ks < 4; ks++) {
            qa[ks][0] = Qs[(r0 + gp    ) * 36 + 8 * ks + tg    ];
            qa[ks][1] = Qs[(r0 + gp + 8) * 36 + 8 * ks + tg    ];
            qa[ks][2] = Qs[(r0 + gp    ) * 36 + 8 * ks + 4 + tg];
            qa[ks][3] = Qs[(r0 + gp + 8) * 36 + 8 * ks + 4 + tg];
        }
    }

    float m0 = -INFINITY, m1 = -INFINITY, l0 = 0.f, l1 = 0.f;
    float o[8][4];
    #pragma unroll
    for (int nf = 0; nf < 8; nf++)
        #pragma unroll
        for (int r = 0; r < 4; r++) o[nf][r] = 0.f;

    const int ktmax = (q0 + 127) >> 6;
    const int row0 = qw + gp, row1 = qw + gp + 8;
    int cur = 0;

    for (int kt = 0; kt <= ktmax; kt++) {
        asm volatile("cp.async.wait_group 0;" ::: "memory");
        __syncthreads();

        if (kt < ktmax) {
            fill_kv(cur ^ 1, kt + 1);
            asm volatile("cp.async.commit_group;" ::: "memory");
        }

        const uint32_t* K = Ks + cur * 2304;
        const uint32_t* V = Vs + cur * 2304;
        const int*      M = mk + cur * 64;

        // ---- S = Q @ K^T (16 x 64 per warp) ----
        float sc[8][4];
        #pragma unroll
        for (int nf = 0; nf < 8; nf++)
            #pragma unroll
            for (int r = 0; r < 4; r++) sc[nf][r] = 0.f;

        #pragma unroll
        for (int ks = 0; ks < 4; ks++) {
            #pragma unroll
            for (int nf = 0; nf < 8; nf++) {
                uint32_t b0 = K[(nf * 8 + gp) * 36 + 8 * ks + tg    ];
                uint32_t b1 = K[(nf * 8 + gp) * 36 + 8 * ks + 4 + tg];
                mma_bf16(sc[nf], qa[ks][0], qa[ks][1], qa[ks][2], qa[ks][3], b0, b1);
            }
        }

        // ---- mask + online softmax (scale already folded into Q) ----
        float tm0 = -INFINITY, tm1 = -INFINITY;
        #pragma unroll
        for (int nf = 0; nf < 8; nf++) {
            int cl = nf * 8 + 2 * tg;
            int c  = kt * 64 + cl;
            bool mk0 = M[cl] != 0, mk1 = M[cl + 1] != 0;
            float s0 = sc[nf][0], s1 = sc[nf][1];
            float s2 = sc[nf][2], s3 = sc[nf][3];
            s0 = (c     <= row0 && mk0) ? s0 : -INFINITY;
            s1 = (c + 1 <= row0 && mk1) ? s1 : -INFINITY;
            s2 = (c     <= row1 && mk0) ? s2 : -INFINITY;
            s3 = (c + 1 <= row1 && mk1) ? s3 : -INFINITY;
            sc[nf][0] = s0; sc[nf][1] = s1; sc[nf][2] = s2; sc[nf][3] = s3;
            tm0 = fmaxf(tm0, fmaxf(s0, s1));
            tm1 = fmaxf(tm1, fmaxf(s2, s3));
        }
        tm0 = fmaxf(tm0, __shfl_xor_sync(0xffffffffu, tm0, 1));
        tm0 = fmaxf(tm0, __shfl_xor_sync(0xffffffffu, tm0, 2));
        tm1 = fmaxf(tm1, __shfl_xor_sync(0xffffffffu, tm1, 1));
        tm1 = fmaxf(tm1, __shfl_xor_sync(0xffffffffu, tm1, 2));

        float nm0 = fmaxf(m0, tm0), nm1 = fmaxf(m1, tm1);
        float ne0 = fmaxf(nm0, -1e30f), ne1 = fmaxf(nm1, -1e30f);
        float al0 = __expf(m0 - ne0), al1 = __expf(m1 - ne1);
        m0 = nm0; m1 = nm1;

        float ps0 = 0.f, ps1 = 0.f;
        #pragma unroll
        for (int nf = 0; nf < 8; nf++) {
            float p0 = __expf(sc[nf][0] - ne0);
            float p1 = __expf(sc[nf][1] - ne0);
            float p2 = __expf(sc[nf][2] - ne1);
            float p3 = __expf(sc[nf][3] - ne1);
            sc[nf][0] = p0; sc[nf][1] = p1; sc[nf][2] = p2; sc[nf][3] = p3;
            ps0 += p0 + p1; ps1 += p2 + p3;
        }
        ps0 += __shfl_xor_sync(0xffffffffu, ps0, 1);
        ps0 += __shfl_xor_sync(0xffffffffu, ps0, 2);
        ps1 += __shfl_xor_sync(0xffffffffu, ps1, 1);
        ps1 += __shfl_xor_sync(0xffffffffu, ps1, 2);
        l0 = l0 * al0 + ps0;
        l1 = l1 * al1 + ps1;

        #pragma unroll
        for (int nf = 0; nf < 8; nf++) {
            o[nf][0] *= al0; o[nf][1] *= al0;
            o[nf][2] *= al1; o[nf][3] *= al1;
        }

        // ---- O += P @ V : C-frag == A-frag layout, just pack bf16 pairs ----
        #pragma unroll
        for (int ks = 0; ks < 4; ks++) {
            uint32_t pa0 = packbf(sc[2*ks  ][1], sc[2*ks  ][0]);
            uint32_t pa1 = packbf(sc[2*ks  ][3], sc[2*ks  ][2]);
            uint32_t pa2 = packbf(sc[2*ks+1][1], sc[2*ks+1][0]);
            uint32_t pa3 = packbf(sc[2*ks+1][3], sc[2*ks+1][2]);
            #pragma unroll
            for (int nf = 0; nf < 8; nf++) {
                uint32_t b0 = V[(8 * ks + tg    ) * 72 + nf * 8 + gp];
                uint32_t b1 = V[(8 * ks + 4 + tg) * 72 + nf * 8 + gp];
                mma_bf16(o[nf], pa0, pa1, pa2, pa3, b0, b1);
            }
        }
        cur ^= 1;
    }

    float il0 = 1.0f / fmaxf(l0, 1e-30f);
    float il1 = 1.0f / fmaxf(l1, 1e-30f);
    #pragma unroll
    for (int nf = 0; nf < 8; nf++) {
        int col = h * HDIM + nf * 8 + 2 * tg;
        float2 v0; v0.x = to_tf32(o[nf][0] * il0); v0.y = to_tf32(o[nf][1] * il0);
        *(float2*)(y + (size_t)row0 * DM + col) = v0;
        float2 v1; v1.x = to_tf32(o[nf][2] * il1); v1.y = to_tf32(o[nf][3] * il1);
        *(float2*)(y + (size_t)row1 * DM + col) = v1;
    }
}

// ---------------- launcher ----------------
extern "C" void kernel_launch(void* const* d_in, const int* in_sizes, int n_in,
                              void* d_out, int out_size)
{
    const float* x     = (const float*)d_in[0];
    const int*   amask = (const int*)  d_in[1];
    const float* ln1g  = (const float*)d_in[2];
    const float* ln1b  = (const float*)d_in[3];
    const float* Wqkv  = (const float*)d_in[4];
    const float* bqkv  = (const float*)d_in[5];
    const float* Wo    = (const float*)d_in[6];
    const float* bo    = (const float*)d_in[7];
    const float* ln2g  = (const float*)d_in[8];
    const float* ln2b  = (const float*)d_in[9];
    const float* W1    = (const float*)d_in[10];
    const float* b1    = (const float*)d_in[11];
    const float* W2    = (const float*)d_in[12];
    const float* b2    = (const float*)d_in[13];
    float* out = (float*)d_out;

    void *p_ln, *p_y, *p_x2, *p_ff;
    void *p_wqkv, *p_wo, *p_w1, *p_w2;
    cudaGetSymbolAddress(&p_ln,   g_ln);
    cudaGetSymbolAddress(&p_y,    g_y);
    cudaGetSymbolAddress(&p_x2,   g_x2);
    cudaGetSymbolAddress(&p_ff,   g_ff);
    cudaGetSymbolAddress(&p_wqkv, g_wt_qkv);
    cudaGetSymbolAddress(&p_wo,   g_wt_o);
    cudaGetSymbolAddress(&p_w1,   g_wt_1);
    cudaGetSymbolAddress(&p_w2,   g_wt_2);

    cudaFuncSetAttribute(attn_kernel,
        cudaFuncAttributeMaxDynamicSharedMemorySize, ATTN_SMEM);
    cudaFuncSetAttribute(gemm_any<1>,
        cudaFuncAttributeMaxDynamicSharedMemorySize, G_SMEM);
    cudaFuncSetAttribute(gemm_any<2>,
        cudaFuncAttributeMaxDynamicSharedMemorySize, G_SMEM);
    cudaFuncSetAttribute(gemm_any<3>,
        cudaFuncAttributeMaxDynamicSharedMemorySize, G_SMEM);

    // 0. weight transposes (tf32-rounded, [N,K])
    transpose_kernel<<<dim3(3 * DM / 32, DM / 32), 256>>>(Wqkv, (float*)p_wqkv, DM, 3 * DM);
    transpose_kernel<<<dim3(DM / 32, DM / 32),     256>>>(Wo,   (float*)p_wo,   DM, DM);
    transpose_kernel<<<dim3(DFF / 32, DM / 32),    256>>>(W1,   (float*)p_w1,   DM, DFF);
    transpose_kernel<<<dim3(DM / 32, DFF / 32),    256>>>(W2,   (float*)p_w2,   DFF, DM);

    // 1. LN1
    ln_kernel<<<T_SEQ, 256>>>(x, ln1g, ln1b, (float*)p_ln);
    // 2. QKV -> bf16 Q/K/V buffers (Q pre-scaled by 1/8)
    gemm_any<3><<<dim3(12, 16), 256, G_SMEM>>>((float*)p_ln, (float*)p_wqkv, bqkv, nullptr,
                                               nullptr, T_SEQ, 3 * DM, DM);
    // 3. attention (bf16 mma)
    attn_kernel<<<dim3(32, 16), 256, ATTN_SMEM>>>(amask, (float*)p_y);
    // 4. x2 = x + y @ W_o + b_o
    gemm_any<1><<<dim3(4, 16), 256, G_SMEM>>>((float*)p_y, (float*)p_wo, bo, x,
                                              (float*)p_x2, T_SEQ, DM, DM);
    // 5. LN2
    ln_kernel<<<T_SEQ, 256>>>((float*)p_x2, ln2g, ln2b, (float*)p_ln);
    // 6. ff = gelu(h2 @ W1 + b1)
    gemm_any<2><<<dim3(16, 16), 256, G_SMEM>>>((float*)p_ln, (float*)p_w1, b1, nullptr,
                                               (float*)p_ff, T_SEQ, DFF, DM);
    // 7. out = x2 + ff @ W2 + b2
    gemm_any<1><<<dim3(4, 16), 256, G_SMEM>>>((float*)p_ff, (float*)p_w2, b2, (float*)p_x2,
                                              out, T_SEQ, DM, DFF);
}